// round 1
// baseline (speedup 1.0000x reference)
#include <cuda_runtime.h>
#include <math.h>

#define Bsz 4
#define Tseq 2048
#define Emb 1024
#define HQ 16
#define HKV 4
#define HD 64
#define TOTQ (HQ*HD)            // 1024
#define TOTKV (HKV*HD)          // 256
#define Fqkv (TOTQ + 2*TOTKV)   // 1536
#define Mrows (Bsz*Tseq)        // 8192

// Scratch (no allocations allowed -> __device__ globals)
__device__ float g_qkv[Mrows * Fqkv];          // 50.3 MB raw qkv
__device__ float g_q[Bsz*HQ*Tseq*HD];          // 33.5 MB
__device__ float g_k[Bsz*HKV*Tseq*HD];         // 8.4 MB
__device__ float g_v[Bsz*HKV*Tseq*HD];         // 8.4 MB
__device__ float g_attn[Mrows * TOTQ];         // 33.5 MB

// ---------------------------------------------------------------------------
// Tiled fp32 GEMM, C[M,N] = A[M,K] * B[N,K]^T   (both row-major, K contiguous)
// BM=BN=128, BK=16, 256 threads, 8x8 per thread.
// ---------------------------------------------------------------------------
#define BM 128
#define BN 128
#define BK 16
#define PADW 132

__global__ __launch_bounds__(256)
void gemm_nt_kernel(const float* __restrict__ A, const float* __restrict__ Bw,
                    float* __restrict__ C, int M, int N, int K)
{
    __shared__ float As[BK][PADW];
    __shared__ float Bs[BK][PADW];
    const int tid = threadIdx.x;
    const int bm = blockIdx.y * BM;
    const int bn = blockIdx.x * BN;
    const int tx = tid & 15;
    const int ty = tid >> 4;

    float acc[8][8] = {};

    const int lr = tid >> 2;          // 0..63
    const int lc = (tid & 3) * 4;     // 0,4,8,12
    const float* Aptr = A + (size_t)(bm + lr) * K + lc;
    const float* Bptr = Bw + (size_t)(bn + lr) * K + lc;

    for (int k0 = 0; k0 < K; k0 += BK) {
        #pragma unroll
        for (int l = 0; l < 2; l++) {
            float4 a = *(const float4*)(Aptr + (size_t)l*64*K + k0);
            int r = lr + l*64;
            As[lc+0][r] = a.x; As[lc+1][r] = a.y; As[lc+2][r] = a.z; As[lc+3][r] = a.w;
            float4 b = *(const float4*)(Bptr + (size_t)l*64*K + k0);
            Bs[lc+0][r] = b.x; Bs[lc+1][r] = b.y; Bs[lc+2][r] = b.z; Bs[lc+3][r] = b.w;
        }
        __syncthreads();
        #pragma unroll
        for (int k = 0; k < BK; k++) {
            float ra[8], rb[8];
            *(float4*)&ra[0] = *(const float4*)&As[k][ty*8];
            *(float4*)&ra[4] = *(const float4*)&As[k][ty*8+4];
            *(float4*)&rb[0] = *(const float4*)&Bs[k][tx*4];
            *(float4*)&rb[4] = *(const float4*)&Bs[k][64 + tx*4];
            #pragma unroll
            for (int i = 0; i < 8; i++)
                #pragma unroll
                for (int j = 0; j < 8; j++)
                    acc[i][j] += ra[i] * rb[j];
        }
        __syncthreads();
    }

    #pragma unroll
    for (int i = 0; i < 8; i++) {
        size_t row = (size_t)(bm + ty*8 + i);
        float4 c0 = make_float4(acc[i][0], acc[i][1], acc[i][2], acc[i][3]);
        float4 c1 = make_float4(acc[i][4], acc[i][5], acc[i][6], acc[i][7]);
        *(float4*)&C[row*N + bn + tx*4]      = c0;
        *(float4*)&C[row*N + bn + 64 + tx*4] = c1;
    }
}

// ---------------------------------------------------------------------------
// RoPE + scatter: g_qkv [M,1536] -> g_q [B,HQ,T,D], g_k/g_v [B,HKV,T,D]
// ---------------------------------------------------------------------------
__global__ __launch_bounds__(256)
void rope_scatter_kernel()
{
    const int m = blockIdx.x;
    const int b = m / Tseq, t = m % Tseq;
    const float* row = g_qkv + (size_t)m * Fqkv;
    const float tf = (float)t;

    for (int w = threadIdx.x; w < 896; w += 256) {
        if (w < 512) {                    // Q rope pairs: 16 heads x 32 pairs
            int h = w >> 5, d = w & 31;
            float inv = 1.0f / powf(10000.0f, (float)d * (1.0f/32.0f));
            float ang = tf * inv;
            float sn = sinf(ang), cs = cosf(ang);
            float v1 = row[h*HD + d];
            float v2 = row[h*HD + d + 32];
            float* q = g_q + ((size_t)(b*HQ + h)*Tseq + t)*HD;
            q[d]      = v1*cs - v2*sn;
            q[d + 32] = v2*cs + v1*sn;
        } else if (w < 640) {             // K rope pairs: 4 heads x 32 pairs
            int p = w - 512;
            int h = p >> 5, d = p & 31;
            float inv = 1.0f / powf(10000.0f, (float)d * (1.0f/32.0f));
            float ang = tf * inv;
            float sn = sinf(ang), cs = cosf(ang);
            float v1 = row[TOTQ + h*HD + d];
            float v2 = row[TOTQ + h*HD + d + 32];
            float* k = g_k + ((size_t)(b*HKV + h)*Tseq + t)*HD;
            k[d]      = v1*cs - v2*sn;
            k[d + 32] = v2*cs + v1*sn;
        } else {                           // V copy: 4 heads x 64
            int e = w - 640;
            int h = e >> 6, d = e & 63;
            g_v[((size_t)(b*HKV + h)*Tseq + t)*HD + d] = row[TOTQ + TOTKV + e];
        }
    }
}

// ---------------------------------------------------------------------------
// Causal flash attention, fp32. One block = (b, hq, 64-row q tile).
// 256 threads: thread t -> row r = t/4, owns S/P/O cols {t%4 + 4*i}.
// Smem tiles stride 68 floats (17 float4) for conflict-free LDS.128.
// ---------------------------------------------------------------------------
#define TSTRIDE4 17              // float4 stride (68 floats)
#define ATT_SMEM (4 * 64 * TSTRIDE4 * 16)   // 69632 bytes

__global__ __launch_bounds__(256, 2)
void attn_kernel()
{
    extern __shared__ float4 smem4[];
    float4* Qs = smem4;
    float4* Ks = smem4 + 64*TSTRIDE4;
    float4* Vt = smem4 + 2*64*TSTRIDE4;
    float4* Ps = smem4 + 3*64*TSTRIDE4;

    const int qt = blockIdx.x;     // 0..31
    const int hq = blockIdx.y;     // 0..15
    const int b  = blockIdx.z;     // 0..3
    const int hkv = hq >> 2;
    const int tid = threadIdx.x;
    const int r  = tid >> 2;       // 0..63
    const int cq = tid & 3;        // 0..3

    const float* Qg = g_q + ((size_t)(b*HQ + hq)*Tseq + qt*64) * HD;
    const float* Kg = g_k + ((size_t)(b*HKV + hkv)*Tseq) * HD;
    const float* Vg = g_v + ((size_t)(b*HKV + hkv)*Tseq) * HD;

    const float scale = 0.125f;    // 1/sqrt(64)
    #pragma unroll
    for (int l = 0; l < 4; l++) {
        int e = tid + l*256;
        int rr = e >> 4, d4 = e & 15;
        float4 q = *(const float4*)&Qg[rr*HD + d4*4];
        q.x *= scale; q.y *= scale; q.z *= scale; q.w *= scale;
        Qs[rr*TSTRIDE4 + d4] = q;
    }

    float o[16];
    #pragma unroll
    for (int i = 0; i < 16; i++) o[i] = 0.f;
    float m_run = -INFINITY, l_run = 0.f;

    for (int j = 0; j <= qt; j++) {
        __syncthreads();   // previous iteration's smem reads complete
        #pragma unroll
        for (int l = 0; l < 4; l++) {
            int e = tid + l*256;
            int rr = e >> 4, d4 = e & 15;
            Ks[rr*TSTRIDE4 + d4] = *(const float4*)&Kg[(j*64 + rr)*HD + d4*4];
            float4 v = *(const float4*)&Vg[(j*64 + rr)*HD + d4*4];
            float* vt = (float*)Vt;
            vt[(d4*4+0)*68 + rr] = v.x;
            vt[(d4*4+1)*68 + rr] = v.y;
            vt[(d4*4+2)*68 + rr] = v.z;
            vt[(d4*4+3)*68 + rr] = v.w;
        }
        __syncthreads();

        // S = Q * K^T (scaled)
        float s[16];
        #pragma unroll
        for (int i = 0; i < 16; i++) {
            int c = cq + 4*i;
            float acc = 0.f;
            #pragma unroll
            for (int d4 = 0; d4 < 16; d4++) {
                float4 q = Qs[r*TSTRIDE4 + d4];
                float4 k = Ks[c*TSTRIDE4 + d4];
                acc += q.x*k.x + q.y*k.y + q.z*k.z + q.w*k.w;
            }
            s[i] = acc;
        }
        if (j == qt) {
            #pragma unroll
            for (int i = 0; i < 16; i++)
                if (cq + 4*i > r) s[i] = -INFINITY;
        }

        // online softmax (row spread over 4 consecutive lanes)
        float mloc = s[0];
        #pragma unroll
        for (int i = 1; i < 16; i++) mloc = fmaxf(mloc, s[i]);
        mloc = fmaxf(mloc, __shfl_xor_sync(0xffffffffu, mloc, 1));
        mloc = fmaxf(mloc, __shfl_xor_sync(0xffffffffu, mloc, 2));
        float m_new = fmaxf(m_run, mloc);
        float corr = __expf(m_run - m_new);

        float p[16];
        float lloc = 0.f;
        #pragma unroll
        for (int i = 0; i < 16; i++) {
            p[i] = __expf(s[i] - m_new);
            lloc += p[i];
        }
        lloc += __shfl_xor_sync(0xffffffffu, lloc, 1);
        lloc += __shfl_xor_sync(0xffffffffu, lloc, 2);
        l_run = l_run * corr + lloc;
        m_run = m_new;

        #pragma unroll
        for (int i = 0; i < 16; i++) o[i] *= corr;

        // stage P (rows private to each warp)
        float* ps = (float*)Ps;
        #pragma unroll
        for (int i = 0; i < 16; i++) ps[r*68 + cq + 4*i] = p[i];
        __syncwarp();

        // O += P * V  (V pre-transposed: Vt[d_out][s])
        #pragma unroll
        for (int i = 0; i < 16; i++) {
            int c = cq + 4*i;
            float acc = o[i];
            #pragma unroll
            for (int s4 = 0; s4 < 16; s4++) {
                float4 pp = Ps[r*TSTRIDE4 + s4];
                float4 vv = Vt[c*TSTRIDE4 + s4];
                acc += pp.x*vv.x + pp.y*vv.y + pp.z*vv.z + pp.w*vv.w;
            }
            o[i] = acc;
        }
    }

    const float inv_l = 1.f / l_run;
    float* outp = g_attn + ((size_t)(b*Tseq) + qt*64 + r) * TOTQ + hq*HD;
    #pragma unroll
    for (int i = 0; i < 16; i++)
        outp[cq + 4*i] = o[i] * inv_l;
}

// ---------------------------------------------------------------------------
extern "C" void kernel_launch(void* const* d_in, const int* in_sizes, int n_in,
                              void* d_out, int out_size)
{
    const float* x     = (const float*)d_in[0];
    const float* w_qkv = (const float*)d_in[1];
    const float* w_out = (const float*)d_in[2];
    float* out = (float*)d_out;

    float *qkv_ptr, *attn_ptr;
    cudaGetSymbolAddress((void**)&qkv_ptr, g_qkv);
    cudaGetSymbolAddress((void**)&attn_ptr, g_attn);

    // 1) QKV projection: [8192,1024] x [1536,1024]^T
    gemm_nt_kernel<<<dim3(Fqkv/BN, Mrows/BM), 256>>>(x, w_qkv, qkv_ptr,
                                                     Mrows, Fqkv, Emb);
    // 2) RoPE + head scatter
    rope_scatter_kernel<<<Mrows, 256>>>();

    // 3) causal GQA attention
    cudaFuncSetAttribute(attn_kernel,
                         cudaFuncAttributeMaxDynamicSharedMemorySize, ATT_SMEM);
    attn_kernel<<<dim3(Tseq/64, HQ, Bsz), 256, ATT_SMEM>>>();

    // 4) output projection: [8192,1024] x [1024,1024]^T
    gemm_nt_kernel<<<dim3(TOTQ/BN, Mrows/BM), 256>>>(attn_ptr, w_out, out,
                                                     Mrows, TOTQ, Emb);
}

// round 4
// speedup vs baseline: 3.7432x; 3.7432x over previous
#include <cuda_runtime.h>
#include <cuda_fp16.h>
#include <math.h>

#define Bsz 4
#define Tseq 2048
#define Emb 1024
#define HQ 16
#define HKV 4
#define HD 64
#define TOTQ (HQ*HD)            // 1024
#define TOTKV (HKV*HD)          // 256
#define Fqkv (TOTQ + 2*TOTKV)   // 1536
#define Mrows (Bsz*Tseq)        // 8192

// Scratch (no allocations allowed -> __device__ globals)
__device__ float g_qkv[Mrows * Fqkv];
__device__ float g_q[Bsz*HQ*Tseq*HD];
__device__ float g_k[Bsz*HKV*Tseq*HD];
__device__ float g_v[Bsz*HKV*Tseq*HD];
__device__ float g_attn[Mrows * TOTQ];

// ---------------------------------------------------------------------------
// helpers
// ---------------------------------------------------------------------------
__device__ __forceinline__ unsigned f2tf32(float f) {
    unsigned u;
    asm("cvt.rna.tf32.f32 %0, %1;" : "=r"(u) : "f"(f));
    return u;
}

__device__ __forceinline__ void mma_tf32(float* c, const unsigned* a,
                                         unsigned b0, unsigned b1) {
    asm volatile(
        "mma.sync.aligned.m16n8k8.row.col.f32.tf32.tf32.f32 "
        "{%0,%1,%2,%3}, {%4,%5,%6,%7}, {%8,%9}, {%0,%1,%2,%3};"
        : "+f"(c[0]), "+f"(c[1]), "+f"(c[2]), "+f"(c[3])
        : "r"(a[0]), "r"(a[1]), "r"(a[2]), "r"(a[3]), "r"(b0), "r"(b1));
}

__device__ __forceinline__ void mma_f16(float* c, const unsigned* a,
                                        unsigned b0, unsigned b1) {
    asm volatile(
        "mma.sync.aligned.m16n8k16.row.col.f32.f16.f16.f32 "
        "{%0,%1,%2,%3}, {%4,%5,%6,%7}, {%8,%9}, {%0,%1,%2,%3};"
        : "+f"(c[0]), "+f"(c[1]), "+f"(c[2]), "+f"(c[3])
        : "r"(a[0]), "r"(a[1]), "r"(a[2]), "r"(a[3]), "r"(b0), "r"(b1));
}

// ---------------------------------------------------------------------------
// tf32 tensor-core GEMM: C[M,N] = A[M,K] * B[N,K]^T  (row-major, K contig)
// 128x128x32 tile, 8 warps (4m x 2n), each warp 32x64 via m16n8k8.
// ---------------------------------------------------------------------------
#define GSTR 36   // smem stride (words), conflict-free frag loads

__global__ __launch_bounds__(256)
void gemm_tc(const float* __restrict__ A, const float* __restrict__ Bw,
             float* __restrict__ C, int M, int N, int K)
{
    __shared__ unsigned As[128*GSTR];
    __shared__ unsigned Bs[128*GSTR];

    const int tid = threadIdx.x;
    const int lane = tid & 31;
    const int wid = tid >> 5;
    const int gid = lane >> 2;
    const int tig = lane & 3;
    const int wm = wid & 3;       // 0..3 -> 32-row slab
    const int wn = wid >> 2;      // 0..1 -> 64-col slab
    const int bm = blockIdx.y * 128;
    const int bn = blockIdx.x * 128;

    float c[2][8][4] = {};

    const int lr = tid >> 3;            // 0..31
    const int lc = (tid & 7) * 4;       // 0..28
    const float* Ap = A + (size_t)(bm + lr) * K + lc;
    const float* Bp = Bw + (size_t)(bn + lr) * K + lc;

    for (int k0 = 0; k0 < K; k0 += 32) {
        #pragma unroll
        for (int l = 0; l < 4; l++) {
            float4 a = *(const float4*)(Ap + (size_t)(l*32) * K + k0);
            int r = lr + l*32;
            unsigned* d = &As[r*GSTR + lc];
            d[0] = f2tf32(a.x); d[1] = f2tf32(a.y);
            d[2] = f2tf32(a.z); d[3] = f2tf32(a.w);
            float4 b = *(const float4*)(Bp + (size_t)(l*32) * K + k0);
            unsigned* e = &Bs[r*GSTR + lc];
            e[0] = f2tf32(b.x); e[1] = f2tf32(b.y);
            e[2] = f2tf32(b.z); e[3] = f2tf32(b.w);
        }
        __syncthreads();
        #pragma unroll
        for (int ks = 0; ks < 4; ks++) {
            const int kk = ks*8;
            unsigned aF[2][4];
            #pragma unroll
            for (int m = 0; m < 2; m++) {
                int rb = wm*32 + m*16;
                aF[m][0] = As[(rb+gid  )*GSTR + kk+tig];
                aF[m][1] = As[(rb+gid+8)*GSTR + kk+tig];
                aF[m][2] = As[(rb+gid  )*GSTR + kk+tig+4];
                aF[m][3] = As[(rb+gid+8)*GSTR + kk+tig+4];
            }
            #pragma unroll
            for (int j = 0; j < 8; j++) {
                int rbn = wn*64 + j*8;
                unsigned b0 = Bs[(rbn+gid)*GSTR + kk+tig];
                unsigned b1 = Bs[(rbn+gid)*GSTR + kk+tig+4];
                mma_tf32(c[0][j], aF[0], b0, b1);
                mma_tf32(c[1][j], aF[1], b0, b1);
            }
        }
        __syncthreads();
    }

    #pragma unroll
    for (int m = 0; m < 2; m++) {
        size_t r0 = (size_t)(bm + wm*32 + m*16 + gid);
        #pragma unroll
        for (int j = 0; j < 8; j++) {
            int cc = bn + wn*64 + j*8 + tig*2;
            *(float2*)&C[r0*N + cc]     = make_float2(c[m][j][0], c[m][j][1]);
            *(float2*)&C[(r0+8)*N + cc] = make_float2(c[m][j][2], c[m][j][3]);
        }
    }
}

// ---------------------------------------------------------------------------
// RoPE + scatter: g_qkv [M,1536] -> g_q, g_k, g_v
// ---------------------------------------------------------------------------
__global__ __launch_bounds__(256)
void rope_scatter_kernel()
{
    const int m = blockIdx.x;
    const int b = m / Tseq, t = m % Tseq;
    const float* row = g_qkv + (size_t)m * Fqkv;
    const float tf = (float)t;

    for (int w = threadIdx.x; w < 896; w += 256) {
        if (w < 512) {                    // Q rope: 16 heads x 32 pairs
            int h = w >> 5, d = w & 31;
            float inv = 1.0f / powf(10000.0f, (float)d * (1.0f/32.0f));
            float ang = tf * inv;
            float sn = sinf(ang), cs = cosf(ang);
            float v1 = row[h*HD + d];
            float v2 = row[h*HD + d + 32];
            float* q = g_q + ((size_t)(b*HQ + h)*Tseq + t)*HD;
            q[d]      = v1*cs - v2*sn;
            q[d + 32] = v2*cs + v1*sn;
        } else if (w < 640) {             // K rope: 4 heads x 32 pairs
            int p = w - 512;
            int h = p >> 5, d = p & 31;
            float inv = 1.0f / powf(10000.0f, (float)d * (1.0f/32.0f));
            float ang = tf * inv;
            float sn = sinf(ang), cs = cosf(ang);
            float v1 = row[TOTQ + h*HD + d];
            float v2 = row[TOTQ + h*HD + d + 32];
            float* k = g_k + ((size_t)(b*HKV + h)*Tseq + t)*HD;
            k[d]      = v1*cs - v2*sn;
            k[d + 32] = v2*cs + v1*sn;
        } else {                          // V copy
            int e = w - 640;
            int h = e >> 6, d = e & 63;
            g_v[((size_t)(b*HKV + h)*Tseq + t)*HD + d] = row[TOTQ + TOTKV + e];
        }
    }
}

// ---------------------------------------------------------------------------
// Tensor-core causal flash attention.
// Block = (qt, hq, b), 4 warps, warp w owns q rows [w*16, w*16+16).
// S: tf32 m16n8k8 (Q pre-scaled + tf32-rounded). PV: fp16 m16n8k16,
// P packed from S C-frags (layout-exact), V staged transposed as half.
// ---------------------------------------------------------------------------
#define QSTR 68     // f32 words per row (conflict-free)
#define VSTR 72     // halves per row of Vt

__global__ __launch_bounds__(128, 3)
void attn_tc()
{
    __shared__ unsigned Qs[64*QSTR];
    __shared__ unsigned Ks[64*QSTR];
    __shared__ __half   Vt[64*VSTR];

    const int qt = blockIdx.x;
    const int hq = blockIdx.y;
    const int b  = blockIdx.z;
    const int hkv = hq >> 2;
    const int tid = threadIdx.x;
    const int lane = tid & 31;
    const int warp = tid >> 5;
    const int gid = lane >> 2;
    const int tig = lane & 3;
    const int q0 = warp * 16;

    const float* Qg = g_q + ((size_t)(b*HQ + hq)*Tseq + qt*64) * HD;
    const float* Kg0 = g_k + ((size_t)(b*HKV + hkv)*Tseq) * HD;
    const float* Vg0 = g_v + ((size_t)(b*HKV + hkv)*Tseq) * HD;

    // load Q tile (scaled, tf32-rounded)
    const int r  = tid >> 1;          // 0..63
    const int cb = (tid & 1) * 32;    // 0 or 32
    #pragma unroll
    for (int l = 0; l < 8; l++) {
        float4 q = *(const float4*)&Qg[r*HD + cb + l*4];
        unsigned* d = &Qs[r*QSTR + cb + l*4];
        d[0] = f2tf32(q.x * 0.125f); d[1] = f2tf32(q.y * 0.125f);
        d[2] = f2tf32(q.z * 0.125f); d[3] = f2tf32(q.w * 0.125f);
    }
    __syncthreads();

    // Q fragments, resident for the whole KV loop
    unsigned qa[8][4];
    #pragma unroll
    for (int ks = 0; ks < 8; ks++) {
        qa[ks][0] = Qs[(q0+gid  )*QSTR + ks*8 + tig];
        qa[ks][1] = Qs[(q0+gid+8)*QSTR + ks*8 + tig];
        qa[ks][2] = Qs[(q0+gid  )*QSTR + ks*8 + tig+4];
        qa[ks][3] = Qs[(q0+gid+8)*QSTR + ks*8 + tig+4];
    }

    float o[8][4];
    #pragma unroll
    for (int j = 0; j < 8; j++)
        #pragma unroll
        for (int e = 0; e < 4; e++) o[j][e] = 0.f;
    float mA = -INFINITY, mB = -INFINITY, lA = 0.f, lB = 0.f;

    for (int j = 0; j <= qt; j++) {
        __syncthreads();
        const float* Kg = Kg0 + (size_t)(j*64) * HD;
        const float* Vg = Vg0 + (size_t)(j*64) * HD;
        #pragma unroll
        for (int l = 0; l < 8; l++) {
            float4 kv = *(const float4*)&Kg[r*HD + cb + l*4];
            unsigned* d = &Ks[r*QSTR + cb + l*4];
            d[0] = f2tf32(kv.x); d[1] = f2tf32(kv.y);
            d[2] = f2tf32(kv.z); d[3] = f2tf32(kv.w);
            float4 vv = *(const float4*)&Vg[r*HD + cb + l*4];
            Vt[(cb+l*4+0)*VSTR + r] = __float2half(vv.x);
            Vt[(cb+l*4+1)*VSTR + r] = __float2half(vv.y);
            Vt[(cb+l*4+2)*VSTR + r] = __float2half(vv.z);
            Vt[(cb+l*4+3)*VSTR + r] = __float2half(vv.w);
        }
        __syncthreads();

        // S = Qs * Ks^T
        float s[8][4];
        #pragma unroll
        for (int jn = 0; jn < 8; jn++) {
            s[jn][0] = s[jn][1] = s[jn][2] = s[jn][3] = 0.f;
            #pragma unroll
            for (int ks = 0; ks < 8; ks++) {
                unsigned b0 = Ks[(jn*8+gid)*QSTR + ks*8 + tig];
                unsigned b1 = Ks[(jn*8+gid)*QSTR + ks*8 + tig+4];
                mma_tf32(s[jn], qa[ks], b0, b1);
            }
        }

        if (j == qt) {   // causal mask within diagonal tile
            #pragma unroll
            for (int jn = 0; jn < 8; jn++) {
                #pragma unroll
                for (int e = 0; e < 2; e++) {
                    int col = jn*8 + tig*2 + e;
                    if (col > q0+gid)   s[jn][e]   = -INFINITY;
                    if (col > q0+gid+8) s[jn][2+e] = -INFINITY;
                }
            }
        }

        // online softmax (rows gid / gid+8, spread over the quad)
        float ma = -INFINITY, mb = -INFINITY;
        #pragma unroll
        for (int jn = 0; jn < 8; jn++) {
            ma = fmaxf(ma, fmaxf(s[jn][0], s[jn][1]));
            mb = fmaxf(mb, fmaxf(s[jn][2], s[jn][3]));
        }
        ma = fmaxf(ma, __shfl_xor_sync(0xffffffffu, ma, 1));
        ma = fmaxf(ma, __shfl_xor_sync(0xffffffffu, ma, 2));
        mb = fmaxf(mb, __shfl_xor_sync(0xffffffffu, mb, 1));
        mb = fmaxf(mb, __shfl_xor_sync(0xffffffffu, mb, 2));

        float mnA = fmaxf(mA, ma), mnB = fmaxf(mB, mb);
        float cA = __expf(mA - mnA), cB = __expf(mB - mnB);

        float la = 0.f, lb = 0.f;
        #pragma unroll
        for (int jn = 0; jn < 8; jn++) {
            s[jn][0] = __expf(s[jn][0] - mnA);
            s[jn][1] = __expf(s[jn][1] - mnA);
            s[jn][2] = __expf(s[jn][2] - mnB);
            s[jn][3] = __expf(s[jn][3] - mnB);
            la += s[jn][0] + s[jn][1];
            lb += s[jn][2] + s[jn][3];
        }
        la += __shfl_xor_sync(0xffffffffu, la, 1);
        la += __shfl_xor_sync(0xffffffffu, la, 2);
        lb += __shfl_xor_sync(0xffffffffu, lb, 1);
        lb += __shfl_xor_sync(0xffffffffu, lb, 2);
        lA = lA*cA + la;  mA = mnA;
        lB = lB*cB + lb;  mB = mnB;

        #pragma unroll
        for (int jd = 0; jd < 8; jd++) {
            o[jd][0] *= cA; o[jd][1] *= cA;
            o[jd][2] *= cB; o[jd][3] *= cB;
        }

        // pack P as fp16 A-fragments (C-frag pair -> m16n8k16 A-frag)
        unsigned pa[4][4];
        #pragma unroll
        for (int kc = 0; kc < 4; kc++) {
            __half2 h;
            h = __floats2half2_rn(s[2*kc][0],   s[2*kc][1]);   pa[kc][0] = *(unsigned*)&h;
            h = __floats2half2_rn(s[2*kc][2],   s[2*kc][3]);   pa[kc][1] = *(unsigned*)&h;
            h = __floats2half2_rn(s[2*kc+1][0], s[2*kc+1][1]); pa[kc][2] = *(unsigned*)&h;
            h = __floats2half2_rn(s[2*kc+1][2], s[2*kc+1][3]); pa[kc][3] = *(unsigned*)&h;
        }

        // O += P * V
        #pragma unroll
        for (int jd = 0; jd < 8; jd++) {
            #pragma unroll
            for (int kc = 0; kc < 4; kc++) {
                unsigned b0 = *(const unsigned*)&Vt[(jd*8+gid)*VSTR + kc*16 + 2*tig];
                unsigned b1 = *(const unsigned*)&Vt[(jd*8+gid)*VSTR + kc*16 + 2*tig + 8];
                mma_f16(o[jd], pa[kc], b0, b1);
            }
        }
    }

    const float invA = 1.f / lA, invB = 1.f / lB;
    float* op = g_attn + ((size_t)(b*Tseq + qt*64 + q0 + gid)) * TOTQ + hq*HD;
    #pragma unroll
    for (int jd = 0; jd < 8; jd++) {
        int col = jd*8 + tig*2;
        *(float2*)&op[col] = make_float2(o[jd][0]*invA, o[jd][1]*invA);
        *(float2*)&op[(size_t)8*TOTQ + col] = make_float2(o[jd][2]*invB, o[jd][3]*invB);
    }
}

// ---------------------------------------------------------------------------
extern "C" void kernel_launch(void* const* d_in, const int* in_sizes, int n_in,
                              void* d_out, int out_size)
{
    const float* x     = (const float*)d_in[0];
    const float* w_qkv = (const float*)d_in[1];
    const float* w_out = (const float*)d_in[2];
    float* out = (float*)d_out;

    float *qkv_ptr, *attn_ptr;
    cudaGetSymbolAddress((void**)&qkv_ptr, g_qkv);
    cudaGetSymbolAddress((void**)&attn_ptr, g_attn);

    // 1) QKV projection: [8192,1024] x [1536,1024]^T
    gemm_tc<<<dim3(Fqkv/128, Mrows/128), 256>>>(x, w_qkv, qkv_ptr,
                                                Mrows, Fqkv, Emb);
    // 2) RoPE + head scatter
    rope_scatter_kernel<<<Mrows, 256>>>();

    // 3) causal GQA flash attention (tensor cores)
    attn_tc<<<dim3(Tseq/64, HQ, Bsz), 128>>>();

    // 4) output projection: [8192,1024] x [1024,1024]^T
    gemm_tc<<<dim3(TOTQ/128, Mrows/128), 256>>>(attn_ptr, w_out, out,
                                                Mrows, TOTQ, Emb);
}

// round 5
// speedup vs baseline: 7.7910x; 2.0814x over previous
#include <cuda_runtime.h>
#include <cuda_fp16.h>
#include <math.h>

#define Bsz 4
#define Tseq 2048
#define Emb 1024
#define HQ 16
#define HKV 4
#define HD 64
#define TOTQ (HQ*HD)            // 1024
#define TOTKV (HKV*HD)          // 256
#define Fqkv (TOTQ + 2*TOTKV)   // 1536
#define Mrows (Bsz*Tseq)        // 8192
#define QSCALE 0.1803368801111204f   // 0.125 * log2(e)

// Scratch (no allocations allowed -> __device__ globals)
__device__ float  g_qkv[Mrows * Fqkv];
__device__ __half g_qh[Bsz*HQ*Tseq*HD];
__device__ __half g_kh[Bsz*HKV*Tseq*HD];
__device__ __half g_vh[Bsz*HKV*Tseq*HD];
__device__ __half g_attnh[Mrows * TOTQ];
__device__ float  g_cos[Tseq*32];
__device__ float  g_sin[Tseq*32];

// ---------------------------------------------------------------------------
// helpers
// ---------------------------------------------------------------------------
__device__ __forceinline__ void mma_f16(float* c, const unsigned* a,
                                        unsigned b0, unsigned b1) {
    asm volatile(
        "mma.sync.aligned.m16n8k16.row.col.f32.f16.f16.f32 "
        "{%0,%1,%2,%3}, {%4,%5,%6,%7}, {%8,%9}, {%0,%1,%2,%3};"
        : "+f"(c[0]), "+f"(c[1]), "+f"(c[2]), "+f"(c[3])
        : "r"(a[0]), "r"(a[1]), "r"(a[2]), "r"(a[3]), "r"(b0), "r"(b1));
}

__device__ __forceinline__ void ldsm_x4(unsigned* r, const void* p) {
    unsigned addr = (unsigned)__cvta_generic_to_shared(p);
    asm volatile("ldmatrix.sync.aligned.m8n8.x4.shared.b16 {%0,%1,%2,%3}, [%4];"
        : "=r"(r[0]), "=r"(r[1]), "=r"(r[2]), "=r"(r[3]) : "r"(addr));
}

__device__ __forceinline__ void ldsm_x4_t(unsigned* r, const void* p) {
    unsigned addr = (unsigned)__cvta_generic_to_shared(p);
    asm volatile("ldmatrix.sync.aligned.m8n8.x4.trans.shared.b16 {%0,%1,%2,%3}, [%4];"
        : "=r"(r[0]), "=r"(r[1]), "=r"(r[2]), "=r"(r[3]) : "r"(addr));
}

__device__ __forceinline__ float ex2(float x) {
    float y;
    asm("ex2.approx.ftz.f32 %0, %1;" : "=f"(y) : "f"(x));
    return y;
}

__device__ __forceinline__ unsigned h2u(float a, float b) {
    __half2 h = __floats2half2_rn(a, b);
    return *(unsigned*)&h;
}

// ---------------------------------------------------------------------------
// fp16 tensor-core GEMM: C[M,N] = A[M,K] * B[N,K]^T  (row-major, K contig)
// 128x128x32 tile, 8 warps (4m x 2n). ldmatrix.x4 fragment loads.
// A gmem dtype: float (AH=false) or half (AH=true). B float. C float.
// ---------------------------------------------------------------------------
#define GSTR 40   // halves per smem row (80B: conflict-free ldmatrix)

template<bool AH>
__global__ __launch_bounds__(256)
void gemm_tc(const void* __restrict__ Ain, const float* __restrict__ Bw,
             float* __restrict__ C, int M, int N, int K)
{
    __shared__ __half As[128*GSTR];
    __shared__ __half Bs[128*GSTR];

    const int tid = threadIdx.x;
    const int lane = tid & 31;
    const int wid = tid >> 5;
    const int g = lane >> 2;
    const int t = lane & 3;
    const int wm = wid & 3;
    const int wn = wid >> 2;
    const int bm = blockIdx.y * 128;
    const int bn = blockIdx.x * 128;

    float c[2][8][4] = {};

    const int lr = tid >> 3;            // 0..31
    const int lc = (tid & 7) * 4;       // 0..28

    // precomputed ldmatrix lane addresses (row/col components)
    const int a_row = (lane & 7) + ((lane & 8) ? 8 : 0);
    const int a_col = (lane & 16) ? 8 : 0;
    const int b_row = (lane & 7) + ((lane & 16) ? 8 : 0);
    const int b_col = (lane & 8) ? 8 : 0;

    for (int k0 = 0; k0 < K; k0 += 32) {
        #pragma unroll
        for (int l = 0; l < 4; l++) {
            int r = lr + l*32;
            if (AH) {
                const __half* Ap = (const __half*)Ain + (size_t)(bm + r) * K + k0 + lc;
                *(uint2*)&As[r*GSTR + lc] = *(const uint2*)Ap;
            } else {
                float4 a = *(const float4*)((const float*)Ain + (size_t)(bm + r) * K + k0 + lc);
                *(uint2*)&As[r*GSTR + lc] = make_uint2(h2u(a.x, a.y), h2u(a.z, a.w));
            }
            float4 b = *(const float4*)(Bw + (size_t)(bn + r) * K + k0 + lc);
            *(uint2*)&Bs[r*GSTR + lc] = make_uint2(h2u(b.x, b.y), h2u(b.z, b.w));
        }
        __syncthreads();
        #pragma unroll
        for (int kc = 0; kc < 2; kc++) {
            unsigned aF[2][4];
            #pragma unroll
            for (int m = 0; m < 2; m++) {
                int rb = wm*32 + m*16;
                ldsm_x4(aF[m], &As[(rb + a_row)*GSTR + kc*16 + a_col]);
            }
            #pragma unroll
            for (int jp = 0; jp < 4; jp++) {
                unsigned bF[4];
                ldsm_x4(bF, &Bs[(wn*64 + jp*16 + b_row)*GSTR + kc*16 + b_col]);
                mma_f16(c[0][2*jp],   aF[0], bF[0], bF[1]);
                mma_f16(c[0][2*jp+1], aF[0], bF[2], bF[3]);
                mma_f16(c[1][2*jp],   aF[1], bF[0], bF[1]);
                mma_f16(c[1][2*jp+1], aF[1], bF[2], bF[3]);
            }
        }
        __syncthreads();
    }

    #pragma unroll
    for (int m = 0; m < 2; m++) {
        size_t r0 = (size_t)(bm + wm*32 + m*16 + g);
        #pragma unroll
        for (int j = 0; j < 8; j++) {
            int cc = bn + wn*64 + j*8 + t*2;
            *(float2*)&C[r0*N + cc]     = make_float2(c[m][j][0], c[m][j][1]);
            *(float2*)&C[(r0+8)*N + cc] = make_float2(c[m][j][2], c[m][j][3]);
        }
    }
}

// ---------------------------------------------------------------------------
// RoPE cos/sin table (accurate sinf/cosf/powf, tiny kernel)
// ---------------------------------------------------------------------------
__global__ void rope_table_kernel()
{
    int i = blockIdx.x * blockDim.x + threadIdx.x;
    if (i < Tseq*32) {
        int tt = i >> 5, d = i & 31;
        float inv = 1.0f / powf(10000.0f, (float)d * (1.0f/32.0f));
        float ang = (float)tt * inv;
        g_cos[i] = cosf(ang);
        g_sin[i] = sinf(ang);
    }
}

// ---------------------------------------------------------------------------
// RoPE + scatter to half: g_qkv [M,1536] -> g_qh (pre-scaled), g_kh, g_vh
// ---------------------------------------------------------------------------
__global__ __launch_bounds__(256)
void rope_scatter_kernel()
{
    const int m = blockIdx.x;
    const int b = m / Tseq, tpos = m % Tseq;
    const float* row = g_qkv + (size_t)m * Fqkv;
    const float* cs_t = g_cos + tpos*32;
    const float* sn_t = g_sin + tpos*32;

    for (int w = threadIdx.x; w < 896; w += 256) {
        if (w < 512) {                    // Q rope: 16 heads x 32 pairs
            int h = w >> 5, d = w & 31;
            float cs = cs_t[d], sn = sn_t[d];
            float v1 = row[h*HD + d];
            float v2 = row[h*HD + d + 32];
            __half* q = g_qh + ((size_t)(b*HQ + h)*Tseq + tpos)*HD;
            q[d]      = __float2half((v1*cs - v2*sn) * QSCALE);
            q[d + 32] = __float2half((v2*cs + v1*sn) * QSCALE);
        } else if (w < 640) {             // K rope: 4 heads x 32 pairs
            int p = w - 512;
            int h = p >> 5, d = p & 31;
            float cs = cs_t[d], sn = sn_t[d];
            float v1 = row[TOTQ + h*HD + d];
            float v2 = row[TOTQ + h*HD + d + 32];
            __half* k = g_kh + ((size_t)(b*HKV + h)*Tseq + tpos)*HD;
            k[d]      = __float2half(v1*cs - v2*sn);
            k[d + 32] = __float2half(v2*cs + v1*sn);
        } else {                          // V copy
            int e = w - 640;
            int h = e >> 6, d = e & 63;
            g_vh[((size_t)(b*HKV + h)*Tseq + tpos)*HD + d] =
                __float2half(row[TOTQ + TOTKV + e]);
        }
    }
}

// ---------------------------------------------------------------------------
// fp16 tensor-core causal flash attention with KV shared across the GQA group.
// Block = (qt, hkv, b), 8 warps / 256 threads. Warp w: head hkv*4 + (w&3),
// q rows (w>>2)*32 .. +31 (two m16 tiles). K/V tiles loaded once per block.
// S,PV: m16n8k16 fp16 mma; softmax in log2 domain (Q pre-scaled by 0.125*log2e);
// V B-frags via ldmatrix.trans (no manual transpose).
// ---------------------------------------------------------------------------
#define KSTR 72     // halves per smem row (144B: conflict-free ldmatrix)

__global__ __launch_bounds__(256)
void attn_tc()
{
    __shared__ __half Ks[64*KSTR];
    __shared__ __half Vs[64*KSTR];

    const int qt  = (int)gridDim.x - 1 - (int)blockIdx.x;  // big tiles first
    const int hkv = blockIdx.y;
    const int b   = blockIdx.z;
    const int tid = threadIdx.x;
    const int lane = tid & 31;
    const int warp = tid >> 5;
    const int g = lane >> 2;
    const int t = lane & 3;
    const int h  = hkv*4 + (warp & 3);
    const int mh = warp >> 2;              // 0/1 -> rows 0-31 / 32-63

    // ldmatrix lane address components
    const int kb_row = (lane & 7) + ((lane & 16) ? 8 : 0);  // K (non-trans B)
    const int kb_col = (lane & 8) ? 8 : 0;
    const int vb_row = (lane & 7) + ((lane & 8) ? 8 : 0);   // V (trans B)
    const int vb_col = (lane & 16) ? 8 : 0;

    // Q fragments straight from gmem (half, pre-scaled)
    const __half* Qg = g_qh + ((size_t)((b*HQ + h)*Tseq + qt*64 + mh*32))*HD;
    unsigned qa[2][4][4];
    #pragma unroll
    for (int mt = 0; mt < 2; mt++)
        #pragma unroll
        for (int kc = 0; kc < 4; kc++) {
            const __half* base = Qg + (mt*16)*HD + kc*16;
            qa[mt][kc][0] = *(const unsigned*)&base[(g  )*HD + 2*t];
            qa[mt][kc][1] = *(const unsigned*)&base[(g+8)*HD + 2*t];
            qa[mt][kc][2] = *(const unsigned*)&base[(g  )*HD + 2*t + 8];
            qa[mt][kc][3] = *(const unsigned*)&base[(g+8)*HD + 2*t + 8];
        }

    float o[2][8][4] = {};
    float mx[2][2] = {{-INFINITY,-INFINITY},{-INFINITY,-INFINITY}};
    float ls[2][2] = {{0.f,0.f},{0.f,0.f}};

    const __half* Kg0 = g_kh + ((size_t)(b*HKV + hkv)*Tseq)*HD;
    const __half* Vg0 = g_vh + ((size_t)(b*HKV + hkv)*Tseq)*HD;

    const int r  = tid >> 2;        // 0..63
    const int c0 = (tid & 3) * 16;  // halves

    for (int j = 0; j <= qt; j++) {
        __syncthreads();
        {
            const uint4* ks = (const uint4*)(Kg0 + (size_t)(j*64 + r)*HD + c0);
            uint4 k0v = ks[0], k1v = ks[1];
            *(uint2*)&Ks[r*KSTR + c0     ] = make_uint2(k0v.x, k0v.y);
            *(uint2*)&Ks[r*KSTR + c0 + 4 ] = make_uint2(k0v.z, k0v.w);
            *(uint2*)&Ks[r*KSTR + c0 + 8 ] = make_uint2(k1v.x, k1v.y);
            *(uint2*)&Ks[r*KSTR + c0 + 12] = make_uint2(k1v.z, k1v.w);
            const uint4* vs = (const uint4*)(Vg0 + (size_t)(j*64 + r)*HD + c0);
            uint4 v0v = vs[0], v1v = vs[1];
            *(uint2*)&Vs[r*KSTR + c0     ] = make_uint2(v0v.x, v0v.y);
            *(uint2*)&Vs[r*KSTR + c0 + 4 ] = make_uint2(v0v.z, v0v.w);
            *(uint2*)&Vs[r*KSTR + c0 + 8 ] = make_uint2(v1v.x, v1v.y);
            *(uint2*)&Vs[r*KSTR + c0 + 12] = make_uint2(v1v.z, v1v.w);
        }
        __syncthreads();

        #pragma unroll
        for (int mt = 0; mt < 2; mt++) {
            // ---- S = Q * K^T (log2 domain) ----
            float s[8][4] = {};
            #pragma unroll
            for (int kc = 0; kc < 4; kc++) {
                #pragma unroll
                for (int jp = 0; jp < 4; jp++) {
                    unsigned bF[4];
                    ldsm_x4(bF, &Ks[(jp*16 + kb_row)*KSTR + kc*16 + kb_col]);
                    mma_f16(s[2*jp],   qa[mt][kc], bF[0], bF[1]);
                    mma_f16(s[2*jp+1], qa[mt][kc], bF[2], bF[3]);
                }
            }

            if (j == qt) {   // causal mask within diagonal tile
                int rowA = qt*64 + mh*32 + mt*16 + g;
                #pragma unroll
                for (int jn = 0; jn < 8; jn++) {
                    #pragma unroll
                    for (int e = 0; e < 2; e++) {
                        int col = j*64 + jn*8 + t*2 + e;
                        if (col > rowA)     s[jn][e]   = -INFINITY;
                        if (col > rowA + 8) s[jn][2+e] = -INFINITY;
                    }
                }
            }

            // ---- online softmax (base-2) ----
            float ma = -INFINITY, mb = -INFINITY;
            #pragma unroll
            for (int jn = 0; jn < 8; jn++) {
                ma = fmaxf(ma, fmaxf(s[jn][0], s[jn][1]));
                mb = fmaxf(mb, fmaxf(s[jn][2], s[jn][3]));
            }
            ma = fmaxf(ma, __shfl_xor_sync(0xffffffffu, ma, 1));
            ma = fmaxf(ma, __shfl_xor_sync(0xffffffffu, ma, 2));
            mb = fmaxf(mb, __shfl_xor_sync(0xffffffffu, mb, 1));
            mb = fmaxf(mb, __shfl_xor_sync(0xffffffffu, mb, 2));

            float mnA = fmaxf(mx[mt][0], ma), mnB = fmaxf(mx[mt][1], mb);
            float cA = ex2(mx[mt][0] - mnA), cB = ex2(mx[mt][1] - mnB);

            float la = 0.f, lb = 0.f;
            #pragma unroll
            for (int jn = 0; jn < 8; jn++) {
                s[jn][0] = ex2(s[jn][0] - mnA);
                s[jn][1] = ex2(s[jn][1] - mnA);
                s[jn][2] = ex2(s[jn][2] - mnB);
                s[jn][3] = ex2(s[jn][3] - mnB);
                la += s[jn][0] + s[jn][1];
                lb += s[jn][2] + s[jn][3];
            }
            la += __shfl_xor_sync(0xffffffffu, la, 1);
            la += __shfl_xor_sync(0xffffffffu, la, 2);
            lb += __shfl_xor_sync(0xffffffffu, lb, 1);
            lb += __shfl_xor_sync(0xffffffffu, lb, 2);
            ls[mt][0] = ls[mt][0]*cA + la;  mx[mt][0] = mnA;
            ls[mt][1] = ls[mt][1]*cB + lb;  mx[mt][1] = mnB;

            #pragma unroll
            for (int jd = 0; jd < 8; jd++) {
                o[mt][jd][0] *= cA; o[mt][jd][1] *= cA;
                o[mt][jd][2] *= cB; o[mt][jd][3] *= cB;
            }

            // pack P as fp16 A-fragments
            unsigned pa[4][4];
            #pragma unroll
            for (int kc = 0; kc < 4; kc++) {
                pa[kc][0] = h2u(s[2*kc][0],   s[2*kc][1]);
                pa[kc][1] = h2u(s[2*kc][2],   s[2*kc][3]);
                pa[kc][2] = h2u(s[2*kc+1][0], s[2*kc+1][1]);
                pa[kc][3] = h2u(s[2*kc+1][2], s[2*kc+1][3]);
            }

            // ---- O += P * V (V B-frags via ldmatrix.trans) ----
            #pragma unroll
            for (int kc = 0; kc < 4; kc++) {
                #pragma unroll
                for (int jp = 0; jp < 4; jp++) {
                    unsigned bF[4];
                    ldsm_x4_t(bF, &Vs[(kc*16 + vb_row)*KSTR + jp*16 + vb_col]);
                    mma_f16(o[mt][2*jp],   pa[kc], bF[0], bF[1]);
                    mma_f16(o[mt][2*jp+1], pa[kc], bF[2], bF[3]);
                }
            }
        }
    }

    // epilogue: normalize + store half
    #pragma unroll
    for (int mt = 0; mt < 2; mt++) {
        float invA = 1.f / ls[mt][0], invB = 1.f / ls[mt][1];
        size_t row0 = (size_t)(b*Tseq + qt*64 + mh*32 + mt*16 + g);
        __half* op = g_attnh + row0*TOTQ + h*HD;
        #pragma unroll
        for (int jd = 0; jd < 8; jd++) {
            int col = jd*8 + t*2;
            *(unsigned*)&op[col] = h2u(o[mt][jd][0]*invA, o[mt][jd][1]*invA);
            *(unsigned*)&op[(size_t)8*TOTQ + col] = h2u(o[mt][jd][2]*invB, o[mt][jd][3]*invB);
        }
    }
}

// ---------------------------------------------------------------------------
extern "C" void kernel_launch(void* const* d_in, const int* in_sizes, int n_in,
                              void* d_out, int out_size)
{
    const float* x     = (const float*)d_in[0];
    const float* w_qkv = (const float*)d_in[1];
    const float* w_out = (const float*)d_in[2];
    float* out = (float*)d_out;

    float *qkv_ptr;
    __half *attnh_ptr;
    cudaGetSymbolAddress((void**)&qkv_ptr, g_qkv);
    cudaGetSymbolAddress((void**)&attnh_ptr, g_attnh);

    // 0) rope cos/sin table (independent of gemm1)
    rope_table_kernel<<<64, 1024>>>();

    // 1) QKV projection: [8192,1024] x [1536,1024]^T (fp32 in, fp32 out)
    gemm_tc<false><<<dim3(Fqkv/128, Mrows/128), 256>>>(x, w_qkv, qkv_ptr,
                                                       Mrows, Fqkv, Emb);
    // 2) RoPE + scatter to half (Q pre-scaled by 0.125*log2e)
    rope_scatter_kernel<<<Mrows, 256>>>();

    // 3) causal GQA flash attention, KV shared per head-group
    attn_tc<<<dim3(Tseq/64, HKV, Bsz), 256>>>();

    // 4) output projection: half A x fp32 B -> fp32 out
    gemm_tc<true><<<dim3(TOTQ/128, Mrows/128), 256>>>(attnh_ptr, w_out, out,
                                                      Mrows, TOTQ, Emb);
}

// round 7
// speedup vs baseline: 8.2786x; 1.0626x over previous
#include <cuda_runtime.h>
#include <cuda_fp16.h>
#include <math.h>

#define Bsz 4
#define Tseq 2048
#define Emb 1024
#define HQ 16
#define HKV 4
#define HD 64
#define TOTQ (HQ*HD)            // 1024
#define TOTKV (HKV*HD)          // 256
#define Fqkv (TOTQ + 2*TOTKV)   // 1536
#define Mrows (Bsz*Tseq)        // 8192
#define QSCALE 0.1803368801111204f   // 0.125 * log2(e)

// Scratch (no allocations allowed -> __device__ globals)
__device__ __half g_xh[Mrows*Emb];
__device__ __half g_wqkvh[Fqkv*Emb];
__device__ __half g_wouth[TOTQ*Emb];
__device__ __half g_qh[Bsz*HQ*Tseq*HD];
__device__ __half g_kh[Bsz*HKV*Tseq*HD];
__device__ __half g_vh[Bsz*HKV*Tseq*HD];
__device__ __half g_attnh[Mrows * TOTQ];
__device__ float  g_cos[Tseq*32];
__device__ float  g_sin[Tseq*32];

// ---------------------------------------------------------------------------
// helpers
// ---------------------------------------------------------------------------
__device__ __forceinline__ void mma_f16(float* c, const unsigned* a,
                                        unsigned b0, unsigned b1) {
    asm volatile(
        "mma.sync.aligned.m16n8k16.row.col.f32.f16.f16.f32 "
        "{%0,%1,%2,%3}, {%4,%5,%6,%7}, {%8,%9}, {%0,%1,%2,%3};"
        : "+f"(c[0]), "+f"(c[1]), "+f"(c[2]), "+f"(c[3])
        : "r"(a[0]), "r"(a[1]), "r"(a[2]), "r"(a[3]), "r"(b0), "r"(b1));
}

__device__ __forceinline__ void ldsm_x4(unsigned* r, const void* p) {
    unsigned addr = (unsigned)__cvta_generic_to_shared(p);
    asm volatile("ldmatrix.sync.aligned.m8n8.x4.shared.b16 {%0,%1,%2,%3}, [%4];"
        : "=r"(r[0]), "=r"(r[1]), "=r"(r[2]), "=r"(r[3]) : "r"(addr));
}

__device__ __forceinline__ void ldsm_x4_t(unsigned* r, const void* p) {
    unsigned addr = (unsigned)__cvta_generic_to_shared(p);
    asm volatile("ldmatrix.sync.aligned.m8n8.x4.trans.shared.b16 {%0,%1,%2,%3}, [%4];"
        : "=r"(r[0]), "=r"(r[1]), "=r"(r[2]), "=r"(r[3]) : "r"(addr));
}

__device__ __forceinline__ void cp16(void* s, const void* g) {
    unsigned sa = (unsigned)__cvta_generic_to_shared(s);
    asm volatile("cp.async.cg.shared.global [%0], [%1], 16;" :: "r"(sa), "l"(g));
}
#define CP_COMMIT() asm volatile("cp.async.commit_group;")
#define CP_WAIT0()  asm volatile("cp.async.wait_group 0;")
#define CP_WAIT1()  asm volatile("cp.async.wait_group 1;")

__device__ __forceinline__ float ex2(float x) {
    float y;
    asm("ex2.approx.ftz.f32 %0, %1;" : "=f"(y) : "f"(x));
    return y;
}

__device__ __forceinline__ unsigned h2u(float a, float b) {
    __half2 h = __floats2half2_rn(a, b);
    return *(unsigned*)&h;
}

// ---------------------------------------------------------------------------
// fp32 -> fp16 bulk convert
// ---------------------------------------------------------------------------
__global__ __launch_bounds__(256)
void f2h_kernel(const float4* __restrict__ in, uint2* __restrict__ out, int n4)
{
    int i = blockIdx.x * blockDim.x + threadIdx.x;
    if (i < n4) {
        float4 a = in[i];
        out[i] = make_uint2(h2u(a.x, a.y), h2u(a.z, a.w));
    }
}

// ---------------------------------------------------------------------------
// RoPE cos/sin table
// ---------------------------------------------------------------------------
__global__ void rope_table_kernel()
{
    int i = blockIdx.x * blockDim.x + threadIdx.x;
    if (i < Tseq*32) {
        int tt = i >> 5, d = i & 31;
        float inv = 1.0f / powf(10000.0f, (float)d * (1.0f/32.0f));
        float ang = (float)tt * inv;
        g_cos[i] = cosf(ang);
        g_sin[i] = sinf(ang);
    }
}

// ---------------------------------------------------------------------------
// fp16 GEMM: C[M,N] = A[M,K]*B[N,K]^T, 128x128x32 tiles, 8 warps,
// cp.async 2-stage double buffer, ldmatrix fragment loads.
// ROPE=true: fused RoPE + head-scatter epilogue (QKV projection) -> g_qh/kh/vh.
// ROPE=false: plain fp32 C store.
// ---------------------------------------------------------------------------
#define GSTR 40   // halves per smem row

template<bool ROPE>
__global__ __launch_bounds__(256)
void gemm_h(const __half* __restrict__ A, const __half* __restrict__ Bw,
            float* __restrict__ C, int M, int N, int K)
{
    __shared__ __half As[2][128*GSTR];
    __shared__ __half Bs[2][128*GSTR];

    const int tid = threadIdx.x;
    const int lane = tid & 31;
    const int wid = tid >> 5;
    const int g = lane >> 2;
    const int t = lane & 3;
    const int wm = wid & 3;
    const int wn = wid >> 2;
    const int bm = blockIdx.y * 128;
    const int bn = blockIdx.x * 128;

    const int lr = tid >> 1;          // 0..127
    const int lc = (tid & 1) * 16;    // 0 or 16 halves
    const __half* Ap = A + (size_t)(bm + lr) * K + lc;
    const __half* Bp = Bw + (size_t)(bn + lr) * K + lc;

    const int a_row = (lane & 7) + ((lane & 8) ? 8 : 0);
    const int a_col = (lane & 16) ? 8 : 0;
    const int b_row = (lane & 7) + ((lane & 16) ? 8 : 0);
    const int b_col = (lane & 8) ? 8 : 0;

    float c[2][8][4] = {};

    // stage 0 load
    cp16(&As[0][lr*GSTR + lc],     Ap);
    cp16(&As[0][lr*GSTR + lc + 8], Ap + 8);
    cp16(&Bs[0][lr*GSTR + lc],     Bp);
    cp16(&Bs[0][lr*GSTR + lc + 8], Bp + 8);
    CP_COMMIT();

    const int NK = K / 32;
    for (int ks = 0; ks < NK; ks++) {
        if (ks + 1 < NK) {
            int nb = (ks + 1) & 1;
            int k0 = (ks + 1) * 32;
            cp16(&As[nb][lr*GSTR + lc],     Ap + k0);
            cp16(&As[nb][lr*GSTR + lc + 8], Ap + k0 + 8);
            cp16(&Bs[nb][lr*GSTR + lc],     Bp + k0);
            cp16(&Bs[nb][lr*GSTR + lc + 8], Bp + k0 + 8);
            CP_COMMIT();
            CP_WAIT1();
        } else {
            CP_WAIT0();
        }
        __syncthreads();
        const __half* as = As[ks & 1];
        const __half* bs = Bs[ks & 1];
        #pragma unroll
        for (int kc = 0; kc < 2; kc++) {
            unsigned aF[2][4];
            #pragma unroll
            for (int m = 0; m < 2; m++)
                ldsm_x4(aF[m], &as[(wm*32 + m*16 + a_row)*GSTR + kc*16 + a_col]);
            #pragma unroll
            for (int jp = 0; jp < 4; jp++) {
                unsigned bF[4];
                ldsm_x4(bF, &bs[(wn*64 + jp*16 + b_row)*GSTR + kc*16 + b_col]);
                mma_f16(c[0][2*jp],   aF[0], bF[0], bF[1]);
                mma_f16(c[0][2*jp+1], aF[0], bF[2], bF[3]);
                mma_f16(c[1][2*jp],   aF[1], bF[0], bF[1]);
                mma_f16(c[1][2*jp+1], aF[1], bF[2], bF[3]);
            }
        }
        __syncthreads();
    }

    if (!ROPE) {
        #pragma unroll
        for (int m = 0; m < 2; m++) {
            size_t r0 = (size_t)(bm + wm*32 + m*16 + g);
            #pragma unroll
            for (int j = 0; j < 8; j++) {
                int cc = bn + wn*64 + j*8 + t*2;
                *(float2*)&C[r0*N + cc]     = make_float2(c[m][j][0], c[m][j][1]);
                *(float2*)&C[(r0+8)*N + cc] = make_float2(c[m][j][2], c[m][j][3]);
            }
        }
    } else {
        // fused RoPE + scatter. Thread's cols j and j+4 are the (d, d+32) pair.
        const int colb = bn + wn*64;   // 64-aligned -> one head
        #pragma unroll
        for (int m = 0; m < 2; m++) {
            #pragma unroll
            for (int rr = 0; rr < 2; rr++) {
                int row = bm + wm*32 + m*16 + g + rr*8;
                int e0 = rr*2;
                int tpos = row & (Tseq-1);
                int bi = row >> 11;
                if (colb < TOTQ) {
                    int h = colb >> 6;
                    __half* q = g_qh + ((size_t)(bi*HQ + h)*Tseq + tpos)*HD;
                    #pragma unroll
                    for (int j = 0; j < 4; j++) {
                        int d = j*8 + t*2;
                        float2 cs = *(const float2*)&g_cos[tpos*32 + d];
                        float2 sn = *(const float2*)&g_sin[tpos*32 + d];
                        float v1x = c[m][j][e0],   v1y = c[m][j][e0+1];
                        float v2x = c[m][j+4][e0], v2y = c[m][j+4][e0+1];
                        *(unsigned*)&q[d] = h2u((v1x*cs.x - v2x*sn.x)*QSCALE,
                                                (v1y*cs.y - v2y*sn.y)*QSCALE);
                        *(unsigned*)&q[d+32] = h2u((v2x*cs.x + v1x*sn.x)*QSCALE,
                                                   (v2y*cs.y + v1y*sn.y)*QSCALE);
                    }
                } else if (colb < TOTQ + TOTKV) {
                    int h = (colb - TOTQ) >> 6;
                    __half* k = g_kh + ((size_t)(bi*HKV + h)*Tseq + tpos)*HD;
                    #pragma unroll
                    for (int j = 0; j < 4; j++) {
                        int d = j*8 + t*2;
                        float2 cs = *(const float2*)&g_cos[tpos*32 + d];
                        float2 sn = *(const float2*)&g_sin[tpos*32 + d];
                        float v1x = c[m][j][e0],   v1y = c[m][j][e0+1];
                        float v2x = c[m][j+4][e0], v2y = c[m][j+4][e0+1];
                        *(unsigned*)&k[d] = h2u(v1x*cs.x - v2x*sn.x,
                                                v1y*cs.y - v2y*sn.y);
                        *(unsigned*)&k[d+32] = h2u(v2x*cs.x + v1x*sn.x,
                                                   v2y*cs.y + v1y*sn.y);
                    }
                } else {
                    int h = (colb - TOTQ - TOTKV) >> 6;
                    __half* v = g_vh + ((size_t)(bi*HKV + h)*Tseq + tpos)*HD;
                    #pragma unroll
                    for (int j = 0; j < 8; j++) {
                        int d = j*8 + t*2;
                        *(unsigned*)&v[d] = h2u(c[m][j][e0], c[m][j][e0+1]);
                    }
                }
            }
        }
    }
}

// ---------------------------------------------------------------------------
// fp16 causal flash attention, KV shared across GQA group.
// Block = (qt, hkv, b), 8 warps. Warp w: head hkv*4+(w&3), rows (w>>2)*32..+31.
// cp.async 2-stage K/V double buffer; K/V fragments hoisted across both
// 16-row Q tiles (mt); softmax in log2 domain.
// ---------------------------------------------------------------------------
#define KSTR 72     // halves per smem row

__global__ __launch_bounds__(256)
void attn_tc()
{
    __shared__ __half Ks[2][64*KSTR];
    __shared__ __half Vs[2][64*KSTR];

    const int qt  = (int)gridDim.x - 1 - (int)blockIdx.x;  // big tiles first
    const int hkv = blockIdx.y;
    const int b   = blockIdx.z;
    const int tid = threadIdx.x;
    const int lane = tid & 31;
    const int warp = tid >> 5;
    const int g = lane >> 2;
    const int t = lane & 3;
    const int h  = hkv*4 + (warp & 3);
    const int mh = warp >> 2;

    const int kb_row = (lane & 7) + ((lane & 16) ? 8 : 0);
    const int kb_col = (lane & 8) ? 8 : 0;
    const int vb_row = (lane & 7) + ((lane & 8) ? 8 : 0);
    const int vb_col = (lane & 16) ? 8 : 0;

    // Q fragments (half, pre-scaled by 0.125*log2e)
    const __half* Qg = g_qh + ((size_t)((b*HQ + h)*Tseq + qt*64 + mh*32))*HD;
    unsigned qa[2][4][4];
    #pragma unroll
    for (int mt = 0; mt < 2; mt++)
        #pragma unroll
        for (int kc = 0; kc < 4; kc++) {
            const __half* base = Qg + (mt*16)*HD + kc*16;
            qa[mt][kc][0] = *(const unsigned*)&base[(g  )*HD + 2*t];
            qa[mt][kc][1] = *(const unsigned*)&base[(g+8)*HD + 2*t];
            qa[mt][kc][2] = *(const unsigned*)&base[(g  )*HD + 2*t + 8];
            qa[mt][kc][3] = *(const unsigned*)&base[(g+8)*HD + 2*t + 8];
        }

    float o[2][8][4] = {};
    float mx[2][2] = {{-INFINITY,-INFINITY},{-INFINITY,-INFINITY}};
    float ls[2][2] = {{0.f,0.f},{0.f,0.f}};

    const __half* Kg0 = g_kh + ((size_t)(b*HKV + hkv)*Tseq)*HD;
    const __half* Vg0 = g_vh + ((size_t)(b*HKV + hkv)*Tseq)*HD;

    const int r  = tid >> 2;        // 0..63
    const int c0 = (tid & 3) * 16;  // halves

    // stage 0 loads
    {
        const __half* kg = Kg0 + (size_t)r*HD + c0;
        const __half* vg = Vg0 + (size_t)r*HD + c0;
        cp16(&Ks[0][r*KSTR + c0],     kg);
        cp16(&Ks[0][r*KSTR + c0 + 8], kg + 8);
        cp16(&Vs[0][r*KSTR + c0],     vg);
        cp16(&Vs[0][r*KSTR + c0 + 8], vg + 8);
        CP_COMMIT();
    }

    for (int j = 0; j <= qt; j++) {
        if (j < qt) {
            int nb = (j + 1) & 1;
            const __half* kg = Kg0 + (size_t)((j+1)*64 + r)*HD + c0;
            const __half* vg = Vg0 + (size_t)((j+1)*64 + r)*HD + c0;
            cp16(&Ks[nb][r*KSTR + c0],     kg);
            cp16(&Ks[nb][r*KSTR + c0 + 8], kg + 8);
            cp16(&Vs[nb][r*KSTR + c0],     vg);
            cp16(&Vs[nb][r*KSTR + c0 + 8], vg + 8);
            CP_COMMIT();
            CP_WAIT1();
        } else {
            CP_WAIT0();
        }
        __syncthreads();
        const __half* ks = Ks[j & 1];
        const __half* vs = Vs[j & 1];

        // ---- S = Q*K^T for both mt tiles (K frags loaded once) ----
        float s[2][8][4] = {};
        #pragma unroll
        for (int kc = 0; kc < 4; kc++) {
            #pragma unroll
            for (int jp = 0; jp < 4; jp++) {
                unsigned bF[4];
                ldsm_x4(bF, &ks[(jp*16 + kb_row)*KSTR + kc*16 + kb_col]);
                mma_f16(s[0][2*jp],   qa[0][kc], bF[0], bF[1]);
                mma_f16(s[0][2*jp+1], qa[0][kc], bF[2], bF[3]);
                mma_f16(s[1][2*jp],   qa[1][kc], bF[0], bF[1]);
                mma_f16(s[1][2*jp+1], qa[1][kc], bF[2], bF[3]);
            }
        }

        // ---- mask + online softmax + pack P, per mt ----
        unsigned pa[2][4][4];
        #pragma unroll
        for (int mt = 0; mt < 2; mt++) {
            if (j == qt) {
                int rowA = mh*32 + mt*16 + g;   // local row within 64
                #pragma unroll
                for (int jn = 0; jn < 8; jn++) {
                    #pragma unroll
                    for (int e = 0; e < 2; e++) {
                        int col = jn*8 + t*2 + e;
                        if (col > rowA)     s[mt][jn][e]   = -INFINITY;
                        if (col > rowA + 8) s[mt][jn][2+e] = -INFINITY;
                    }
                }
            }
            float ma = -INFINITY, mb = -INFINITY;
            #pragma unroll
            for (int jn = 0; jn < 8; jn++) {
                ma = fmaxf(ma, fmaxf(s[mt][jn][0], s[mt][jn][1]));
                mb = fmaxf(mb, fmaxf(s[mt][jn][2], s[mt][jn][3]));
            }
            ma = fmaxf(ma, __shfl_xor_sync(0xffffffffu, ma, 1));
            ma = fmaxf(ma, __shfl_xor_sync(0xffffffffu, ma, 2));
            mb = fmaxf(mb, __shfl_xor_sync(0xffffffffu, mb, 1));
            mb = fmaxf(mb, __shfl_xor_sync(0xffffffffu, mb, 2));

            float mnA = fmaxf(mx[mt][0], ma), mnB = fmaxf(mx[mt][1], mb);
            float cA = ex2(mx[mt][0] - mnA), cB = ex2(mx[mt][1] - mnB);

            float la = 0.f, lb = 0.f;
            #pragma unroll
            for (int jn = 0; jn < 8; jn++) {
                s[mt][jn][0] = ex2(s[mt][jn][0] - mnA);
                s[mt][jn][1] = ex2(s[mt][jn][1] - mnA);
                s[mt][jn][2] = ex2(s[mt][jn][2] - mnB);
                s[mt][jn][3] = ex2(s[mt][jn][3] - mnB);
                la += s[mt][jn][0] + s[mt][jn][1];
                lb += s[mt][jn][2] + s[mt][jn][3];
            }
            la += __shfl_xor_sync(0xffffffffu, la, 1);
            la += __shfl_xor_sync(0xffffffffu, la, 2);
            lb += __shfl_xor_sync(0xffffffffu, lb, 1);
            lb += __shfl_xor_sync(0xffffffffu, lb, 2);
            ls[mt][0] = ls[mt][0]*cA + la;  mx[mt][0] = mnA;
            ls[mt][1] = ls[mt][1]*cB + lb;  mx[mt][1] = mnB;

            #pragma unroll
            for (int jd = 0; jd < 8; jd++) {
                o[mt][jd][0] *= cA; o[mt][jd][1] *= cA;
                o[mt][jd][2] *= cB; o[mt][jd][3] *= cB;
            }
            #pragma unroll
            for (int kc = 0; kc < 4; kc++) {
                pa[mt][kc][0] = h2u(s[mt][2*kc][0],   s[mt][2*kc][1]);
                pa[mt][kc][1] = h2u(s[mt][2*kc][2],   s[mt][2*kc][3]);
                pa[mt][kc][2] = h2u(s[mt][2*kc+1][0], s[mt][2*kc+1][1]);
                pa[mt][kc][3] = h2u(s[mt][2*kc+1][2], s[mt][2*kc+1][3]);
            }
        }

        // ---- O += P*V for both mt (V frags loaded once, trans ldmatrix) ----
        #pragma unroll
        for (int kc = 0; kc < 4; kc++) {
            #pragma unroll
            for (int jp = 0; jp < 4; jp++) {
                unsigned bF[4];
                ldsm_x4_t(bF, &vs[(kc*16 + vb_row)*KSTR + jp*16 + vb_col]);
                mma_f16(o[0][2*jp],   pa[0][kc], bF[0], bF[1]);
                mma_f16(o[0][2*jp+1], pa[0][kc], bF[2], bF[3]);
                mma_f16(o[1][2*jp],   pa[1][kc], bF[0], bF[1]);
                mma_f16(o[1][2*jp+1], pa[1][kc], bF[2], bF[3]);
            }
        }
        __syncthreads();
    }

    // epilogue: normalize + store half
    #pragma unroll
    for (int mt = 0; mt < 2; mt++) {
        float invA = 1.f / ls[mt][0], invB = 1.f / ls[mt][1];
        size_t row0 = (size_t)(b*Tseq + qt*64 + mh*32 + mt*16 + g);
        __half* op = g_attnh + row0*TOTQ + h*HD;
        #pragma unroll
        for (int jd = 0; jd < 8; jd++) {
            int col = jd*8 + t*2;
            *(unsigned*)&op[col] = h2u(o[mt][jd][0]*invA, o[mt][jd][1]*invA);
            *(unsigned*)&op[(size_t)8*TOTQ + col] = h2u(o[mt][jd][2]*invB, o[mt][jd][3]*invB);
        }
    }
}

// ---------------------------------------------------------------------------
extern "C" void kernel_launch(void* const* d_in, const int* in_sizes, int n_in,
                              void* d_out, int out_size)
{
    const float* x     = (const float*)d_in[0];
    const float* w_qkv = (const float*)d_in[1];
    const float* w_out = (const float*)d_in[2];
    float* out = (float*)d_out;

    __half *xh, *wqkvh, *wouth, *attnh;
    cudaGetSymbolAddress((void**)&xh, g_xh);
    cudaGetSymbolAddress((void**)&wqkvh, g_wqkvh);
    cudaGetSymbolAddress((void**)&wouth, g_wouth);
    cudaGetSymbolAddress((void**)&attnh, g_attnh);

    // 0) rope table + fp16 conversions
    rope_table_kernel<<<64, 1024>>>();
    f2h_kernel<<<(Mrows*Emb/4 + 255)/256, 256>>>((const float4*)x, (uint2*)xh, Mrows*Emb/4);
    f2h_kernel<<<(Fqkv*Emb/4 + 255)/256, 256>>>((const float4*)w_qkv, (uint2*)wqkvh, Fqkv*Emb/4);
    f2h_kernel<<<(TOTQ*Emb/4 + 255)/256, 256>>>((const float4*)w_out, (uint2*)wouth, TOTQ*Emb/4);

    // 1) QKV projection with fused RoPE + head scatter
    gemm_h<true><<<dim3(Fqkv/128, Mrows/128), 256>>>(xh, wqkvh, nullptr,
                                                     Mrows, Fqkv, Emb);
    // 2) causal GQA flash attention
    attn_tc<<<dim3(Tseq/64, HKV, Bsz), 256>>>();

    // 3) output projection
    gemm_h<false><<<dim3(TOTQ/128, Mrows/128), 256>>>(attnh, wouth, out,
                                                      Mrows, TOTQ, Emb);
}

// round 9
// speedup vs baseline: 8.3583x; 1.0096x over previous
#include <cuda_runtime.h>
#include <cuda_fp16.h>
#include <math.h>

#define Bsz 4
#define Tseq 2048
#define Emb 1024
#define HQ 16
#define HKV 4
#define HD 64
#define TOTQ (HQ*HD)            // 1024
#define TOTKV (HKV*HD)          // 256
#define Fqkv (TOTQ + 2*TOTKV)   // 1536
#define Mrows (Bsz*Tseq)        // 8192
#define QSCALE 0.1803368801111204f   // 0.125 * log2(e)

// Scratch (no allocations allowed -> __device__ globals)
__device__ __half g_xh[Mrows*Emb];
__device__ __half g_wqkvh[Fqkv*Emb];
__device__ __half g_wouth[TOTQ*Emb];
__device__ __half g_qh[Bsz*HQ*Tseq*HD];
__device__ __half g_kh[Bsz*HKV*Tseq*HD];
__device__ __half g_vh[Bsz*HKV*Tseq*HD];
__device__ __half g_attnh[Mrows * TOTQ];
__device__ float  g_cos[Tseq*32];
__device__ float  g_sin[Tseq*32];

// ---------------------------------------------------------------------------
// helpers
// ---------------------------------------------------------------------------
__device__ __forceinline__ void mma_f16(float* c, const unsigned* a,
                                        unsigned b0, unsigned b1) {
    asm volatile(
        "mma.sync.aligned.m16n8k16.row.col.f32.f16.f16.f32 "
        "{%0,%1,%2,%3}, {%4,%5,%6,%7}, {%8,%9}, {%0,%1,%2,%3};"
        : "+f"(c[0]), "+f"(c[1]), "+f"(c[2]), "+f"(c[3])
        : "r"(a[0]), "r"(a[1]), "r"(a[2]), "r"(a[3]), "r"(b0), "r"(b1));
}

__device__ __forceinline__ void ldsm_x4(unsigned* r, const void* p) {
    unsigned addr = (unsigned)__cvta_generic_to_shared(p);
    asm volatile("ldmatrix.sync.aligned.m8n8.x4.shared.b16 {%0,%1,%2,%3}, [%4];"
        : "=r"(r[0]), "=r"(r[1]), "=r"(r[2]), "=r"(r[3]) : "r"(addr));
}

__device__ __forceinline__ void ldsm_x4_t(unsigned* r, const void* p) {
    unsigned addr = (unsigned)__cvta_generic_to_shared(p);
    asm volatile("ldmatrix.sync.aligned.m8n8.x4.trans.shared.b16 {%0,%1,%2,%3}, [%4];"
        : "=r"(r[0]), "=r"(r[1]), "=r"(r[2]), "=r"(r[3]) : "r"(addr));
}

__device__ __forceinline__ void cp16(void* s, const void* g) {
    unsigned sa = (unsigned)__cvta_generic_to_shared(s);
    asm volatile("cp.async.cg.shared.global [%0], [%1], 16;" :: "r"(sa), "l"(g));
}
#define CP_COMMIT() asm volatile("cp.async.commit_group;")
#define CP_WAIT0()  asm volatile("cp.async.wait_group 0;")
#define CP_WAIT1()  asm volatile("cp.async.wait_group 1;")

__device__ __forceinline__ float ex2(float x) {
    float y;
    asm("ex2.approx.ftz.f32 %0, %1;" : "=f"(y) : "f"(x));
    return y;
}

__device__ __forceinline__ unsigned h2u(float a, float b) {
    __half2 h = __floats2half2_rn(a, b);
    return *(unsigned*)&h;
}

// ---------------------------------------------------------------------------
// fp32 -> fp16 bulk convert
// ---------------------------------------------------------------------------
__global__ __launch_bounds__(256)
void f2h_kernel(const float4* __restrict__ in, uint2* __restrict__ out, int n4)
{
    int i = blockIdx.x * blockDim.x + threadIdx.x;
    if (i < n4) {
        float4 a = in[i];
        out[i] = make_uint2(h2u(a.x, a.y), h2u(a.z, a.w));
    }
}

// ---------------------------------------------------------------------------
// RoPE cos/sin table
// ---------------------------------------------------------------------------
__global__ void rope_table_kernel()
{
    int i = blockIdx.x * blockDim.x + threadIdx.x;
    if (i < Tseq*32) {
        int tt = i >> 5, d = i & 31;
        float inv = 1.0f / powf(10000.0f, (float)d * (1.0f/32.0f));
        float ang = (float)tt * inv;
        g_cos[i] = cosf(ang);
        g_sin[i] = sinf(ang);
    }
}

// ---------------------------------------------------------------------------
// fp16 GEMM: C[M,N] = A[M,K]*B[N,K]^T, 128x128x32 tiles, 8 warps,
// cp.async 2-stage double buffer, ldmatrix fragment loads.
// ROPE=true: fused RoPE + head-scatter epilogue (QKV projection) -> g_qh/kh/vh.
// ROPE=false: plain fp32 C store.
// ---------------------------------------------------------------------------
#define GSTR 40   // halves per smem row

template<bool ROPE>
__global__ __launch_bounds__(256)
void gemm_h(const __half* __restrict__ A, const __half* __restrict__ Bw,
            float* __restrict__ C, int M, int N, int K)
{
    __shared__ __half As[2][128*GSTR];
    __shared__ __half Bs[2][128*GSTR];

    const int tid = threadIdx.x;
    const int lane = tid & 31;
    const int wid = tid >> 5;
    const int g = lane >> 2;
    const int t = lane & 3;
    const int wm = wid & 3;
    const int wn = wid >> 2;
    const int bm = blockIdx.y * 128;
    const int bn = blockIdx.x * 128;

    const int lr = tid >> 1;          // 0..127
    const int lc = (tid & 1) * 16;    // 0 or 16 halves
    const __half* Ap = A + (size_t)(bm + lr) * K + lc;
    const __half* Bp = Bw + (size_t)(bn + lr) * K + lc;

    const int a_row = (lane & 7) + ((lane & 8) ? 8 : 0);
    const int a_col = (lane & 16) ? 8 : 0;
    const int b_row = (lane & 7) + ((lane & 16) ? 8 : 0);
    const int b_col = (lane & 8) ? 8 : 0;

    float c[2][8][4] = {};

    // stage 0 load
    cp16(&As[0][lr*GSTR + lc],     Ap);
    cp16(&As[0][lr*GSTR + lc + 8], Ap + 8);
    cp16(&Bs[0][lr*GSTR + lc],     Bp);
    cp16(&Bs[0][lr*GSTR + lc + 8], Bp + 8);
    CP_COMMIT();

    const int NK = K / 32;
    for (int ks = 0; ks < NK; ks++) {
        if (ks + 1 < NK) {
            int nb = (ks + 1) & 1;
            int k0 = (ks + 1) * 32;
            cp16(&As[nb][lr*GSTR + lc],     Ap + k0);
            cp16(&As[nb][lr*GSTR + lc + 8], Ap + k0 + 8);
            cp16(&Bs[nb][lr*GSTR + lc],     Bp + k0);
            cp16(&Bs[nb][lr*GSTR + lc + 8], Bp + k0 + 8);
            CP_COMMIT();
            CP_WAIT1();
        } else {
            CP_WAIT0();
        }
        __syncthreads();
        const __half* as = As[ks & 1];
        const __half* bs = Bs[ks & 1];
        #pragma unroll
        for (int kc = 0; kc < 2; kc++) {
            unsigned aF[2][4];
            #pragma unroll
            for (int m = 0; m < 2; m++)
                ldsm_x4(aF[m], &as[(wm*32 + m*16 + a_row)*GSTR + kc*16 + a_col]);
            #pragma unroll
            for (int jp = 0; jp < 4; jp++) {
                unsigned bF[4];
                ldsm_x4(bF, &bs[(wn*64 + jp*16 + b_row)*GSTR + kc*16 + b_col]);
                mma_f16(c[0][2*jp],   aF[0], bF[0], bF[1]);
                mma_f16(c[0][2*jp+1], aF[0], bF[2], bF[3]);
                mma_f16(c[1][2*jp],   aF[1], bF[0], bF[1]);
                mma_f16(c[1][2*jp+1], aF[1], bF[2], bF[3]);
            }
        }
        __syncthreads();
    }

    if (!ROPE) {
        #pragma unroll
        for (int m = 0; m < 2; m++) {
            size_t r0 = (size_t)(bm + wm*32 + m*16 + g);
            #pragma unroll
            for (int j = 0; j < 8; j++) {
                int cc = bn + wn*64 + j*8 + t*2;
                *(float2*)&C[r0*N + cc]     = make_float2(c[m][j][0], c[m][j][1]);
                *(float2*)&C[(r0+8)*N + cc] = make_float2(c[m][j][2], c[m][j][3]);
            }
        }
    } else {
        // fused RoPE + scatter. Thread's cols j and j+4 are the (d, d+32) pair.
        const int colb = bn + wn*64;   // 64-aligned -> one head
        #pragma unroll
        for (int m = 0; m < 2; m++) {
            #pragma unroll
            for (int rr = 0; rr < 2; rr++) {
                int row = bm + wm*32 + m*16 + g + rr*8;
                int e0 = rr*2;
                int tpos = row & (Tseq-1);
                int bi = row >> 11;
                if (colb < TOTQ) {
                    int h = colb >> 6;
                    __half* q = g_qh + ((size_t)(bi*HQ + h)*Tseq + tpos)*HD;
                    #pragma unroll
                    for (int j = 0; j < 4; j++) {
                        int d = j*8 + t*2;
                        float2 cs = *(const float2*)&g_cos[tpos*32 + d];
                        float2 sn = *(const float2*)&g_sin[tpos*32 + d];
                        float v1x = c[m][j][e0],   v1y = c[m][j][e0+1];
                        float v2x = c[m][j+4][e0], v2y = c[m][j+4][e0+1];
                        *(unsigned*)&q[d] = h2u((v1x*cs.x - v2x*sn.x)*QSCALE,
                                                (v1y*cs.y - v2y*sn.y)*QSCALE);
                        *(unsigned*)&q[d+32] = h2u((v2x*cs.x + v1x*sn.x)*QSCALE,
                                                   (v2y*cs.y + v1y*sn.y)*QSCALE);
                    }
                } else if (colb < TOTQ + TOTKV) {
                    int h = (colb - TOTQ) >> 6;
                    __half* k = g_kh + ((size_t)(bi*HKV + h)*Tseq + tpos)*HD;
                    #pragma unroll
                    for (int j = 0; j < 4; j++) {
                        int d = j*8 + t*2;
                        float2 cs = *(const float2*)&g_cos[tpos*32 + d];
                        float2 sn = *(const float2*)&g_sin[tpos*32 + d];
                        float v1x = c[m][j][e0],   v1y = c[m][j][e0+1];
                        float v2x = c[m][j+4][e0], v2y = c[m][j+4][e0+1];
                        *(unsigned*)&k[d] = h2u(v1x*cs.x - v2x*sn.x,
                                                v1y*cs.y - v2y*sn.y);
                        *(unsigned*)&k[d+32] = h2u(v2x*cs.x + v1x*sn.x,
                                                   v2y*cs.y + v1y*sn.y);
                    }
                } else {
                    int h = (colb - TOTQ - TOTKV) >> 6;
                    __half* v = g_vh + ((size_t)(bi*HKV + h)*Tseq + tpos)*HD;
                    #pragma unroll
                    for (int j = 0; j < 8; j++) {
                        int d = j*8 + t*2;
                        *(unsigned*)&v[d] = h2u(c[m][j][e0], c[m][j][e0+1]);
                    }
                }
            }
        }
    }
}

// ---------------------------------------------------------------------------
// fp16 causal flash attention, KV shared across GQA group.
// Block = (qt, hkv, b), 8 warps. Warp w: head hkv*4+(w&3), rows (w>>2)*32..+31.
// cp.async 2-stage K/V double buffer. S computed per 16-row tile (transient
// s[8][4] -> no spills); V fragments shared across both tiles via pa[2].
// Softmax in log2 domain (Q pre-scaled by 0.125*log2e).
// ---------------------------------------------------------------------------
#define KSTR 72     // halves per smem row

__global__ __launch_bounds__(256)
void attn_tc()
{
    __shared__ __half Ks[2][64*KSTR];
    __shared__ __half Vs[2][64*KSTR];

    const int qt  = (int)gridDim.x - 1 - (int)blockIdx.x;  // big tiles first
    const int hkv = blockIdx.y;
    const int b   = blockIdx.z;
    const int tid = threadIdx.x;
    const int lane = tid & 31;
    const int warp = tid >> 5;
    const int g = lane >> 2;
    const int t = lane & 3;
    const int h  = hkv*4 + (warp & 3);
    const int mh = warp >> 2;

    const int kb_row = (lane & 7) + ((lane & 16) ? 8 : 0);
    const int kb_col = (lane & 8) ? 8 : 0;
    const int vb_row = (lane & 7) + ((lane & 8) ? 8 : 0);
    const int vb_col = (lane & 16) ? 8 : 0;

    // Q fragments (half, pre-scaled by 0.125*log2e)
    const __half* Qg = g_qh + ((size_t)((b*HQ + h)*Tseq + qt*64 + mh*32))*HD;
    unsigned qa[2][4][4];
    #pragma unroll
    for (int mt = 0; mt < 2; mt++)
        #pragma unroll
        for (int kc = 0; kc < 4; kc++) {
            const __half* base = Qg + (mt*16)*HD + kc*16;
            qa[mt][kc][0] = *(const unsigned*)&base[(g  )*HD + 2*t];
            qa[mt][kc][1] = *(const unsigned*)&base[(g+8)*HD + 2*t];
            qa[mt][kc][2] = *(const unsigned*)&base[(g  )*HD + 2*t + 8];
            qa[mt][kc][3] = *(const unsigned*)&base[(g+8)*HD + 2*t + 8];
        }

    float o[2][8][4] = {};
    float mx[2][2] = {{-INFINITY,-INFINITY},{-INFINITY,-INFINITY}};
    float ls[2][2] = {{0.f,0.f},{0.f,0.f}};

    const __half* Kg0 = g_kh + ((size_t)(b*HKV + hkv)*Tseq)*HD;
    const __half* Vg0 = g_vh + ((size_t)(b*HKV + hkv)*Tseq)*HD;

    const int r  = tid >> 2;        // 0..63
    const int c0 = (tid & 3) * 16;  // halves

    // stage 0 loads
    {
        const __half* kg = Kg0 + (size_t)r*HD + c0;
        const __half* vg = Vg0 + (size_t)r*HD + c0;
        cp16(&Ks[0][r*KSTR + c0],     kg);
        cp16(&Ks[0][r*KSTR + c0 + 8], kg + 8);
        cp16(&Vs[0][r*KSTR + c0],     vg);
        cp16(&Vs[0][r*KSTR + c0 + 8], vg + 8);
        CP_COMMIT();
    }

    for (int j = 0; j <= qt; j++) {
        if (j < qt) {
            int nb = (j + 1) & 1;
            const __half* kg = Kg0 + (size_t)((j+1)*64 + r)*HD + c0;
            const __half* vg = Vg0 + (size_t)((j+1)*64 + r)*HD + c0;
            cp16(&Ks[nb][r*KSTR + c0],     kg);
            cp16(&Ks[nb][r*KSTR + c0 + 8], kg + 8);
            cp16(&Vs[nb][r*KSTR + c0],     vg);
            cp16(&Vs[nb][r*KSTR + c0 + 8], vg + 8);
            CP_COMMIT();
            CP_WAIT1();
        } else {
            CP_WAIT0();
        }
        __syncthreads();
        const __half* ks = Ks[j & 1];
        const __half* vs = Vs[j & 1];

        // ---- per mt: S = Q*K^T, mask, softmax, pack P (s transient) ----
        unsigned pa[2][4][4];
        #pragma unroll
        for (int mt = 0; mt < 2; mt++) {
            float s[8][4] = {};
            #pragma unroll
            for (int kc = 0; kc < 4; kc++) {
                #pragma unroll
                for (int jp = 0; jp < 4; jp++) {
                    unsigned bF[4];
                    ldsm_x4(bF, &ks[(jp*16 + kb_row)*KSTR + kc*16 + kb_col]);
                    mma_f16(s[2*jp],   qa[mt][kc], bF[0], bF[1]);
                    mma_f16(s[2*jp+1], qa[mt][kc], bF[2], bF[3]);
                }
            }

            if (j == qt) {
                int rowA = mh*32 + mt*16 + g;   // local row within 64
                #pragma unroll
                for (int jn = 0; jn < 8; jn++) {
                    #pragma unroll
                    for (int e = 0; e < 2; e++) {
                        int col = jn*8 + t*2 + e;
                        if (col > rowA)     s[jn][e]   = -INFINITY;
                        if (col > rowA + 8) s[jn][2+e] = -INFINITY;
                    }
                }
            }
            float ma = -INFINITY, mb = -INFINITY;
            #pragma unroll
            for (int jn = 0; jn < 8; jn++) {
                ma = fmaxf(ma, fmaxf(s[jn][0], s[jn][1]));
                mb = fmaxf(mb, fmaxf(s[jn][2], s[jn][3]));
            }
            ma = fmaxf(ma, __shfl_xor_sync(0xffffffffu, ma, 1));
            ma = fmaxf(ma, __shfl_xor_sync(0xffffffffu, ma, 2));
            mb = fmaxf(mb, __shfl_xor_sync(0xffffffffu, mb, 1));
            mb = fmaxf(mb, __shfl_xor_sync(0xffffffffu, mb, 2));

            float mnA = fmaxf(mx[mt][0], ma), mnB = fmaxf(mx[mt][1], mb);
            float cA = ex2(mx[mt][0] - mnA), cB = ex2(mx[mt][1] - mnB);

            float la = 0.f, lb = 0.f;
            #pragma unroll
            for (int jn = 0; jn < 8; jn++) {
                s[jn][0] = ex2(s[jn][0] - mnA);
                s[jn][1] = ex2(s[jn][1] - mnA);
                s[jn][2] = ex2(s[jn][2] - mnB);
                s[jn][3] = ex2(s[jn][3] - mnB);
                la += s[jn][0] + s[jn][1];
                lb += s[jn][2] + s[jn][3];
            }
            la += __shfl_xor_sync(0xffffffffu, la, 1);
            la += __shfl_xor_sync(0xffffffffu, la, 2);
            lb += __shfl_xor_sync(0xffffffffu, lb, 1);
            lb += __shfl_xor_sync(0xffffffffu, lb, 2);
            ls[mt][0] = ls[mt][0]*cA + la;  mx[mt][0] = mnA;
            ls[mt][1] = ls[mt][1]*cB + lb;  mx[mt][1] = mnB;

            #pragma unroll
            for (int jd = 0; jd < 8; jd++) {
                o[mt][jd][0] *= cA; o[mt][jd][1] *= cA;
                o[mt][jd][2] *= cB; o[mt][jd][3] *= cB;
            }
            #pragma unroll
            for (int kc = 0; kc < 4; kc++) {
                pa[mt][kc][0] = h2u(s[2*kc][0],   s[2*kc][1]);
                pa[mt][kc][1] = h2u(s[2*kc][2],   s[2*kc][3]);
                pa[mt][kc][2] = h2u(s[2*kc+1][0], s[2*kc+1][1]);
                pa[mt][kc][3] = h2u(s[2*kc+1][2], s[2*kc+1][3]);
            }
        }

        // ---- O += P*V for both mt (V frags loaded once, trans ldmatrix) ----
        #pragma unroll
        for (int kc = 0; kc < 4; kc++) {
            #pragma unroll
            for (int jp = 0; jp < 4; jp++) {
                unsigned bF[4];
                ldsm_x4_t(bF, &vs[(kc*16 + vb_row)*KSTR + jp*16 + vb_col]);
                mma_f16(o[0][2*jp],   pa[0][kc], bF[0], bF[1]);
                mma_f16(o[0][2*jp+1], pa[0][kc], bF[2], bF[3]);
                mma_f16(o[1][2*jp],   pa[1][kc], bF[0], bF[1]);
                mma_f16(o[1][2*jp+1], pa[1][kc], bF[2], bF[3]);
            }
        }
        __syncthreads();
    }

    // epilogue: normalize + store half
    #pragma unroll
    for (int mt = 0; mt < 2; mt++) {
        float invA = 1.f / ls[mt][0], invB = 1.f / ls[mt][1];
        size_t row0 = (size_t)(b*Tseq + qt*64 + mh*32 + mt*16 + g);
        __half* op = g_attnh + row0*TOTQ + h*HD;
        #pragma unroll
        for (int jd = 0; jd < 8; jd++) {
            int col = jd*8 + t*2;
            *(unsigned*)&op[col] = h2u(o[mt][jd][0]*invA, o[mt][jd][1]*invA);
            *(unsigned*)&op[(size_t)8*TOTQ + col] = h2u(o[mt][jd][2]*invB, o[mt][jd][3]*invB);
        }
    }
}

// ---------------------------------------------------------------------------
extern "C" void kernel_launch(void* const* d_in, const int* in_sizes, int n_in,
                              void* d_out, int out_size)
{
    const float* x     = (const float*)d_in[0];
    const float* w_qkv = (const float*)d_in[1];
    const float* w_out = (const float*)d_in[2];
    float* out = (float*)d_out;

    __half *xh, *wqkvh, *wouth, *attnh;
    cudaGetSymbolAddress((void**)&xh, g_xh);
    cudaGetSymbolAddress((void**)&wqkvh, g_wqkvh);
    cudaGetSymbolAddress((void**)&wouth, g_wouth);
    cudaGetSymbolAddress((void**)&attnh, g_attnh);

    // 0) rope table + fp16 conversions
    rope_table_kernel<<<64, 1024>>>();
    f2h_kernel<<<(Mrows*Emb/4 + 255)/256, 256>>>((const float4*)x, (uint2*)xh, Mrows*Emb/4);
    f2h_kernel<<<(Fqkv*Emb/4 + 255)/256, 256>>>((const float4*)w_qkv, (uint2*)wqkvh, Fqkv*Emb/4);
    f2h_kernel<<<(TOTQ*Emb/4 + 255)/256, 256>>>((const float4*)w_out, (uint2*)wouth, TOTQ*Emb/4);

    // 1) QKV projection with fused RoPE + head scatter
    gemm_h<true><<<dim3(Fqkv/128, Mrows/128), 256>>>(xh, wqkvh, nullptr,
                                                     Mrows, Fqkv, Emb);
    // 2) causal GQA flash attention
    attn_tc<<<dim3(Tseq/64, HKV, Bsz), 256>>>();

    // 3) output projection
    gemm_h<false><<<dim3(TOTQ/128, Mrows/128), 256>>>(attnh, wouth, out,
                                                      Mrows, TOTQ, Emb);
}

// round 10
// speedup vs baseline: 8.6037x; 1.0294x over previous
#include <cuda_runtime.h>
#include <cuda_fp16.h>
#include <math.h>

#define Bsz 4
#define Tseq 2048
#define Emb 1024
#define HQ 16
#define HKV 4
#define HD 64
#define TOTQ (HQ*HD)            // 1024
#define TOTKV (HKV*HD)          // 256
#define Fqkv (TOTQ + 2*TOTKV)   // 1536
#define Mrows (Bsz*Tseq)        // 8192
#define QSCALE 0.1803368801111204f   // 0.125 * log2(e)

// Scratch (no allocations allowed -> __device__ globals)
__device__ __half g_xh[Mrows*Emb];
__device__ __half g_wqkvh[Fqkv*Emb];
__device__ __half g_wouth[TOTQ*Emb];
__device__ __half g_qh[Bsz*HQ*Tseq*HD];
__device__ __half g_kh[Bsz*HKV*Tseq*HD];
__device__ __half g_vh[Bsz*HKV*Tseq*HD];
__device__ __half g_attnh[Mrows * TOTQ];
__device__ float  g_cos[Tseq*32];
__device__ float  g_sin[Tseq*32];

// ---------------------------------------------------------------------------
// helpers
// ---------------------------------------------------------------------------
__device__ __forceinline__ void mma_f16(float* c, const unsigned* a,
                                        unsigned b0, unsigned b1) {
    asm volatile(
        "mma.sync.aligned.m16n8k16.row.col.f32.f16.f16.f32 "
        "{%0,%1,%2,%3}, {%4,%5,%6,%7}, {%8,%9}, {%0,%1,%2,%3};"
        : "+f"(c[0]), "+f"(c[1]), "+f"(c[2]), "+f"(c[3])
        : "r"(a[0]), "r"(a[1]), "r"(a[2]), "r"(a[3]), "r"(b0), "r"(b1));
}

__device__ __forceinline__ void ldsm_x4(unsigned* r, const void* p) {
    unsigned addr = (unsigned)__cvta_generic_to_shared(p);
    asm volatile("ldmatrix.sync.aligned.m8n8.x4.shared.b16 {%0,%1,%2,%3}, [%4];"
        : "=r"(r[0]), "=r"(r[1]), "=r"(r[2]), "=r"(r[3]) : "r"(addr));
}

__device__ __forceinline__ void ldsm_x4_t(unsigned* r, const void* p) {
    unsigned addr = (unsigned)__cvta_generic_to_shared(p);
    asm volatile("ldmatrix.sync.aligned.m8n8.x4.trans.shared.b16 {%0,%1,%2,%3}, [%4];"
        : "=r"(r[0]), "=r"(r[1]), "=r"(r[2]), "=r"(r[3]) : "r"(addr));
}

__device__ __forceinline__ void cp16(void* s, const void* g) {
    unsigned sa = (unsigned)__cvta_generic_to_shared(s);
    asm volatile("cp.async.cg.shared.global [%0], [%1], 16;" :: "r"(sa), "l"(g));
}
#define CP_COMMIT() asm volatile("cp.async.commit_group;")
#define CP_WAIT0()  asm volatile("cp.async.wait_group 0;")
#define CP_WAIT1()  asm volatile("cp.async.wait_group 1;")

__device__ __forceinline__ float ex2(float x) {
    float y;
    asm("ex2.approx.ftz.f32 %0, %1;" : "=f"(y) : "f"(x));
    return y;
}

__device__ __forceinline__ unsigned h2u(float a, float b) {
    __half2 h = __floats2half2_rn(a, b);
    return *(unsigned*)&h;
}

// ---------------------------------------------------------------------------
// fp32 -> fp16 bulk convert
// ---------------------------------------------------------------------------
__global__ __launch_bounds__(256)
void f2h_kernel(const float4* __restrict__ in, uint2* __restrict__ out, int n4)
{
    int i = blockIdx.x * blockDim.x + threadIdx.x;
    if (i < n4) {
        float4 a = in[i];
        out[i] = make_uint2(h2u(a.x, a.y), h2u(a.z, a.w));
    }
}

// ---------------------------------------------------------------------------
// RoPE cos/sin table
// ---------------------------------------------------------------------------
__global__ void rope_table_kernel()
{
    int i = blockIdx.x * blockDim.x + threadIdx.x;
    if (i < Tseq*32) {
        int tt = i >> 5, d = i & 31;
        float inv = 1.0f / powf(10000.0f, (float)d * (1.0f/32.0f));
        float ang = (float)tt * inv;
        g_cos[i] = cosf(ang);
        g_sin[i] = sinf(ang);
    }
}

// ---------------------------------------------------------------------------
// fp16 GEMM: C[M,N] = A[M,K]*B[N,K]^T, 128x128x32 tiles, 8 warps,
// cp.async 2-stage double buffer, ldmatrix fragment loads.
// ROPE=true: fused RoPE + head-scatter epilogue (QKV projection) -> g_qh/kh/vh.
// ROPE=false: plain fp32 C store.
// ---------------------------------------------------------------------------
#define GSTR 40   // halves per smem row

template<bool ROPE>
__global__ __launch_bounds__(256)
void gemm_h(const __half* __restrict__ A, const __half* __restrict__ Bw,
            float* __restrict__ C, int M, int N, int K)
{
    __shared__ __half As[2][128*GSTR];
    __shared__ __half Bs[2][128*GSTR];

    const int tid = threadIdx.x;
    const int lane = tid & 31;
    const int wid = tid >> 5;
    const int g = lane >> 2;
    const int t = lane & 3;
    const int wm = wid & 3;
    const int wn = wid >> 2;
    const int bm = blockIdx.y * 128;
    const int bn = blockIdx.x * 128;

    const int lr = tid >> 1;          // 0..127
    const int lc = (tid & 1) * 16;    // 0 or 16 halves
    const __half* Ap = A + (size_t)(bm + lr) * K + lc;
    const __half* Bp = Bw + (size_t)(bn + lr) * K + lc;

    const int a_row = (lane & 7) + ((lane & 8) ? 8 : 0);
    const int a_col = (lane & 16) ? 8 : 0;
    const int b_row = (lane & 7) + ((lane & 16) ? 8 : 0);
    const int b_col = (lane & 8) ? 8 : 0;

    float c[2][8][4] = {};

    // stage 0 load
    cp16(&As[0][lr*GSTR + lc],     Ap);
    cp16(&As[0][lr*GSTR + lc + 8], Ap + 8);
    cp16(&Bs[0][lr*GSTR + lc],     Bp);
    cp16(&Bs[0][lr*GSTR + lc + 8], Bp + 8);
    CP_COMMIT();

    const int NK = K / 32;
    for (int ks = 0; ks < NK; ks++) {
        if (ks + 1 < NK) {
            int nb = (ks + 1) & 1;
            int k0 = (ks + 1) * 32;
            cp16(&As[nb][lr*GSTR + lc],     Ap + k0);
            cp16(&As[nb][lr*GSTR + lc + 8], Ap + k0 + 8);
            cp16(&Bs[nb][lr*GSTR + lc],     Bp + k0);
            cp16(&Bs[nb][lr*GSTR + lc + 8], Bp + k0 + 8);
            CP_COMMIT();
            CP_WAIT1();
        } else {
            CP_WAIT0();
        }
        __syncthreads();
        const __half* as = As[ks & 1];
        const __half* bs = Bs[ks & 1];
        #pragma unroll
        for (int kc = 0; kc < 2; kc++) {
            unsigned aF[2][4];
            #pragma unroll
            for (int m = 0; m < 2; m++)
                ldsm_x4(aF[m], &as[(wm*32 + m*16 + a_row)*GSTR + kc*16 + a_col]);
            #pragma unroll
            for (int jp = 0; jp < 4; jp++) {
                unsigned bF[4];
                ldsm_x4(bF, &bs[(wn*64 + jp*16 + b_row)*GSTR + kc*16 + b_col]);
                mma_f16(c[0][2*jp],   aF[0], bF[0], bF[1]);
                mma_f16(c[0][2*jp+1], aF[0], bF[2], bF[3]);
                mma_f16(c[1][2*jp],   aF[1], bF[0], bF[1]);
                mma_f16(c[1][2*jp+1], aF[1], bF[2], bF[3]);
            }
        }
        __syncthreads();
    }

    if (!ROPE) {
        #pragma unroll
        for (int m = 0; m < 2; m++) {
            size_t r0 = (size_t)(bm + wm*32 + m*16 + g);
            #pragma unroll
            for (int j = 0; j < 8; j++) {
                int cc = bn + wn*64 + j*8 + t*2;
                *(float2*)&C[r0*N + cc]     = make_float2(c[m][j][0], c[m][j][1]);
                *(float2*)&C[(r0+8)*N + cc] = make_float2(c[m][j][2], c[m][j][3]);
            }
        }
    } else {
        // fused RoPE + scatter. Thread's cols j and j+4 are the (d, d+32) pair.
        const int colb = bn + wn*64;   // 64-aligned -> one head
        #pragma unroll
        for (int m = 0; m < 2; m++) {
            #pragma unroll
            for (int rr = 0; rr < 2; rr++) {
                int row = bm + wm*32 + m*16 + g + rr*8;
                int e0 = rr*2;
                int tpos = row & (Tseq-1);
                int bi = row >> 11;
                if (colb < TOTQ) {
                    int h = colb >> 6;
                    __half* q = g_qh + ((size_t)(bi*HQ + h)*Tseq + tpos)*HD;
                    #pragma unroll
                    for (int j = 0; j < 4; j++) {
                        int d = j*8 + t*2;
                        float2 cs = *(const float2*)&g_cos[tpos*32 + d];
                        float2 sn = *(const float2*)&g_sin[tpos*32 + d];
                        float v1x = c[m][j][e0],   v1y = c[m][j][e0+1];
                        float v2x = c[m][j+4][e0], v2y = c[m][j+4][e0+1];
                        *(unsigned*)&q[d] = h2u((v1x*cs.x - v2x*sn.x)*QSCALE,
                                                (v1y*cs.y - v2y*sn.y)*QSCALE);
                        *(unsigned*)&q[d+32] = h2u((v2x*cs.x + v1x*sn.x)*QSCALE,
                                                   (v2y*cs.y + v1y*sn.y)*QSCALE);
                    }
                } else if (colb < TOTQ + TOTKV) {
                    int h = (colb - TOTQ) >> 6;
                    __half* k = g_kh + ((size_t)(bi*HKV + h)*Tseq + tpos)*HD;
                    #pragma unroll
                    for (int j = 0; j < 4; j++) {
                        int d = j*8 + t*2;
                        float2 cs = *(const float2*)&g_cos[tpos*32 + d];
                        float2 sn = *(const float2*)&g_sin[tpos*32 + d];
                        float v1x = c[m][j][e0],   v1y = c[m][j][e0+1];
                        float v2x = c[m][j+4][e0], v2y = c[m][j+4][e0+1];
                        *(unsigned*)&k[d] = h2u(v1x*cs.x - v2x*sn.x,
                                                v1y*cs.y - v2y*sn.y);
                        *(unsigned*)&k[d+32] = h2u(v2x*cs.x + v1x*sn.x,
                                                   v2y*cs.y + v1y*sn.y);
                    }
                } else {
                    int h = (colb - TOTQ - TOTKV) >> 6;
                    __half* v = g_vh + ((size_t)(bi*HKV + h)*Tseq + tpos)*HD;
                    #pragma unroll
                    for (int j = 0; j < 8; j++) {
                        int d = j*8 + t*2;
                        *(unsigned*)&v[d] = h2u(c[m][j][e0], c[m][j][e0+1]);
                    }
                }
            }
        }
    }
}

// ---------------------------------------------------------------------------
// fp16 causal flash attention, KV shared across GQA group.
// Block = (qt, hkv, b), 16 warps / 512 threads. Warp w = (head, 16-row tile):
// head = hkv*4 + (w&3), rows (w>>2)*16 .. +15 of the 64-row Q block.
// Same KV tiles serve all 16 warps (KV traffic unchanged vs 8-warp version)
// but 2x resident warps hide the softmax dependency chain.
// cp.async 2-stage K/V double buffer; softmax in log2 domain.
// ---------------------------------------------------------------------------
#define KSTR 72     // halves per smem row

__global__ __launch_bounds__(512, 1)
void attn_tc()
{
    __shared__ __half Ks[2][64*KSTR];
    __shared__ __half Vs[2][64*KSTR];

    const int qt  = (int)gridDim.x - 1 - (int)blockIdx.x;  // big tiles first
    const int hkv = blockIdx.y;
    const int b   = blockIdx.z;
    const int tid = threadIdx.x;
    const int lane = tid & 31;
    const int warp = tid >> 5;       // 0..15
    const int g = lane >> 2;
    const int t = lane & 3;
    const int h  = hkv*4 + (warp & 3);
    const int mt = warp >> 2;        // 0..3 -> 16-row tile within 64

    const int kb_row = (lane & 7) + ((lane & 16) ? 8 : 0);
    const int kb_col = (lane & 8) ? 8 : 0;
    const int vb_row = (lane & 7) + ((lane & 8) ? 8 : 0);
    const int vb_col = (lane & 16) ? 8 : 0;

    // Q fragments (half, pre-scaled by 0.125*log2e)
    const __half* Qg = g_qh + ((size_t)((b*HQ + h)*Tseq + qt*64 + mt*16))*HD;
    unsigned qa[4][4];
    #pragma unroll
    for (int kc = 0; kc < 4; kc++) {
        const __half* base = Qg + kc*16;
        qa[kc][0] = *(const unsigned*)&base[(g  )*HD + 2*t];
        qa[kc][1] = *(const unsigned*)&base[(g+8)*HD + 2*t];
        qa[kc][2] = *(const unsigned*)&base[(g  )*HD + 2*t + 8];
        qa[kc][3] = *(const unsigned*)&base[(g+8)*HD + 2*t + 8];
    }

    float o[8][4] = {};
    float mxA = -INFINITY, mxB = -INFINITY;
    float lsA = 0.f, lsB = 0.f;

    const __half* Kg0 = g_kh + ((size_t)(b*HKV + hkv)*Tseq)*HD;
    const __half* Vg0 = g_vh + ((size_t)(b*HKV + hkv)*Tseq)*HD;

    const int r  = tid >> 3;        // 0..63
    const int c0 = (tid & 7) * 8;   // halves (16B per thread)

    // stage 0 loads
    cp16(&Ks[0][r*KSTR + c0], Kg0 + (size_t)r*HD + c0);
    cp16(&Vs[0][r*KSTR + c0], Vg0 + (size_t)r*HD + c0);
    CP_COMMIT();

    for (int j = 0; j <= qt; j++) {
        if (j < qt) {
            int nb = (j + 1) & 1;
            cp16(&Ks[nb][r*KSTR + c0], Kg0 + (size_t)((j+1)*64 + r)*HD + c0);
            cp16(&Vs[nb][r*KSTR + c0], Vg0 + (size_t)((j+1)*64 + r)*HD + c0);
            CP_COMMIT();
            CP_WAIT1();
        } else {
            CP_WAIT0();
        }
        __syncthreads();
        const __half* ks = Ks[j & 1];
        const __half* vs = Vs[j & 1];

        // ---- S = Q*K^T (log2 domain) ----
        float s[8][4] = {};
        #pragma unroll
        for (int kc = 0; kc < 4; kc++) {
            #pragma unroll
            for (int jp = 0; jp < 4; jp++) {
                unsigned bF[4];
                ldsm_x4(bF, &ks[(jp*16 + kb_row)*KSTR + kc*16 + kb_col]);
                mma_f16(s[2*jp],   qa[kc], bF[0], bF[1]);
                mma_f16(s[2*jp+1], qa[kc], bF[2], bF[3]);
            }
        }

        if (j == qt) {   // causal mask within diagonal tile
            int rowA = mt*16 + g;   // local row within 64
            #pragma unroll
            for (int jn = 0; jn < 8; jn++) {
                #pragma unroll
                for (int e = 0; e < 2; e++) {
                    int col = jn*8 + t*2 + e;
                    if (col > rowA)     s[jn][e]   = -INFINITY;
                    if (col > rowA + 8) s[jn][2+e] = -INFINITY;
                }
            }
        }

        // ---- online softmax (base-2), rows g / g+8 ----
        float ma = -INFINITY, mb = -INFINITY;
        #pragma unroll
        for (int jn = 0; jn < 8; jn++) {
            ma = fmaxf(ma, fmaxf(s[jn][0], s[jn][1]));
            mb = fmaxf(mb, fmaxf(s[jn][2], s[jn][3]));
        }
        ma = fmaxf(ma, __shfl_xor_sync(0xffffffffu, ma, 1));
        ma = fmaxf(ma, __shfl_xor_sync(0xffffffffu, ma, 2));
        mb = fmaxf(mb, __shfl_xor_sync(0xffffffffu, mb, 1));
        mb = fmaxf(mb, __shfl_xor_sync(0xffffffffu, mb, 2));

        float mnA = fmaxf(mxA, ma), mnB = fmaxf(mxB, mb);
        float cA = ex2(mxA - mnA), cB = ex2(mxB - mnB);

        float la = 0.f, lb = 0.f;
        #pragma unroll
        for (int jn = 0; jn < 8; jn++) {
            s[jn][0] = ex2(s[jn][0] - mnA);
            s[jn][1] = ex2(s[jn][1] - mnA);
            s[jn][2] = ex2(s[jn][2] - mnB);
            s[jn][3] = ex2(s[jn][3] - mnB);
            la += s[jn][0] + s[jn][1];
            lb += s[jn][2] + s[jn][3];
        }
        la += __shfl_xor_sync(0xffffffffu, la, 1);
        la += __shfl_xor_sync(0xffffffffu, la, 2);
        lb += __shfl_xor_sync(0xffffffffu, lb, 1);
        lb += __shfl_xor_sync(0xffffffffu, lb, 2);
        lsA = lsA*cA + la;  mxA = mnA;
        lsB = lsB*cB + lb;  mxB = mnB;

        #pragma unroll
        for (int jd = 0; jd < 8; jd++) {
            o[jd][0] *= cA; o[jd][1] *= cA;
            o[jd][2] *= cB; o[jd][3] *= cB;
        }

        // pack P as fp16 A-fragments
        unsigned pa[4][4];
        #pragma unroll
        for (int kc = 0; kc < 4; kc++) {
            pa[kc][0] = h2u(s[2*kc][0],   s[2*kc][1]);
            pa[kc][1] = h2u(s[2*kc][2],   s[2*kc][3]);
            pa[kc][2] = h2u(s[2*kc+1][0], s[2*kc+1][1]);
            pa[kc][3] = h2u(s[2*kc+1][2], s[2*kc+1][3]);
        }

        // ---- O += P*V (V B-frags via ldmatrix.trans) ----
        #pragma unroll
        for (int kc = 0; kc < 4; kc++) {
            #pragma unroll
            for (int jp = 0; jp < 4; jp++) {
                unsigned bF[4];
                ldsm_x4_t(bF, &vs[(kc*16 + vb_row)*KSTR + jp*16 + vb_col]);
                mma_f16(o[2*jp],   pa[kc], bF[0], bF[1]);
                mma_f16(o[2*jp+1], pa[kc], bF[2], bF[3]);
            }
        }
        __syncthreads();
    }

    // epilogue: normalize + store half
    const float invA = 1.f / lsA, invB = 1.f / lsB;
    size_t row0 = (size_t)(b*Tseq + qt*64 + mt*16 + g);
    __half* op = g_attnh + row0*TOTQ + h*HD;
    #pragma unroll
    for (int jd = 0; jd < 8; jd++) {
        int col = jd*8 + t*2;
        *(unsigned*)&op[col] = h2u(o[jd][0]*invA, o[jd][1]*invA);
        *(unsigned*)&op[(size_t)8*TOTQ + col] = h2u(o[jd][2]*invB, o[jd][3]*invB);
    }
}

// ---------------------------------------------------------------------------
extern "C" void kernel_launch(void* const* d_in, const int* in_sizes, int n_in,
                              void* d_out, int out_size)
{
    const float* x     = (const float*)d_in[0];
    const float* w_qkv = (const float*)d_in[1];
    const float* w_out = (const float*)d_in[2];
    float* out = (float*)d_out;

    __half *xh, *wqkvh, *wouth, *attnh;
    cudaGetSymbolAddress((void**)&xh, g_xh);
    cudaGetSymbolAddress((void**)&wqkvh, g_wqkvh);
    cudaGetSymbolAddress((void**)&wouth, g_wouth);
    cudaGetSymbolAddress((void**)&attnh, g_attnh);

    // 0) rope table + fp16 conversions
    rope_table_kernel<<<64, 1024>>>();
    f2h_kernel<<<(Mrows*Emb/4 + 255)/256, 256>>>((const float4*)x, (uint2*)xh, Mrows*Emb/4);
    f2h_kernel<<<(Fqkv*Emb/4 + 255)/256, 256>>>((const float4*)w_qkv, (uint2*)wqkvh, Fqkv*Emb/4);
    f2h_kernel<<<(TOTQ*Emb/4 + 255)/256, 256>>>((const float4*)w_out, (uint2*)wouth, TOTQ*Emb/4);

    // 1) QKV projection with fused RoPE + head scatter
    gemm_h<true><<<dim3(Fqkv/128, Mrows/128), 256>>>(xh, wqkvh, nullptr,
                                                     Mrows, Fqkv, Emb);
    // 2) causal GQA flash attention (512 threads, 16 warps)
    attn_tc<<<dim3(Tseq/64, HKV, Bsz), 512>>>();

    // 3) output projection
    gemm_h<false><<<dim3(TOTQ/128, Mrows/128), 256>>>(attnh, wouth, out,
                                                      Mrows, TOTQ, Emb);
}

// round 12
// speedup vs baseline: 9.6740x; 1.1244x over previous
#include <cuda_runtime.h>
#include <cuda_fp16.h>
#include <math.h>

#define Bsz 4
#define Tseq 2048
#define Emb 1024
#define HQ 16
#define HKV 4
#define HD 64
#define TOTQ (HQ*HD)            // 1024
#define TOTKV (HKV*HD)          // 256
#define Fqkv (TOTQ + 2*TOTKV)   // 1536
#define Mrows (Bsz*Tseq)        // 8192
#define QSCALE 0.1803368801111204f   // 0.125 * log2(e)

// Scratch (no allocations allowed -> __device__ globals)
__device__ __half g_xh[Mrows*Emb];
__device__ __half g_wqkvh[Fqkv*Emb];
__device__ __half g_wouth[TOTQ*Emb];
__device__ __half g_qh[Bsz*HQ*Tseq*HD];
__device__ __half g_kh[Bsz*HKV*Tseq*HD];
__device__ __half g_vh[Bsz*HKV*Tseq*HD];
__device__ __half g_attnh[Mrows * TOTQ];
__device__ float  g_cos[Tseq*32];
__device__ float  g_sin[Tseq*32];

// ---------------------------------------------------------------------------
// helpers
// ---------------------------------------------------------------------------
__device__ __forceinline__ void mma_f16(float* c, const unsigned* a,
                                        unsigned b0, unsigned b1) {
    asm volatile(
        "mma.sync.aligned.m16n8k16.row.col.f32.f16.f16.f32 "
        "{%0,%1,%2,%3}, {%4,%5,%6,%7}, {%8,%9}, {%0,%1,%2,%3};"
        : "+f"(c[0]), "+f"(c[1]), "+f"(c[2]), "+f"(c[3])
        : "r"(a[0]), "r"(a[1]), "r"(a[2]), "r"(a[3]), "r"(b0), "r"(b1));
}

__device__ __forceinline__ void ldsm_x4(unsigned* r, const void* p) {
    unsigned addr = (unsigned)__cvta_generic_to_shared(p);
    asm volatile("ldmatrix.sync.aligned.m8n8.x4.shared.b16 {%0,%1,%2,%3}, [%4];"
        : "=r"(r[0]), "=r"(r[1]), "=r"(r[2]), "=r"(r[3]) : "r"(addr));
}

__device__ __forceinline__ void ldsm_x4_t(unsigned* r, const void* p) {
    unsigned addr = (unsigned)__cvta_generic_to_shared(p);
    asm volatile("ldmatrix.sync.aligned.m8n8.x4.trans.shared.b16 {%0,%1,%2,%3}, [%4];"
        : "=r"(r[0]), "=r"(r[1]), "=r"(r[2]), "=r"(r[3]) : "r"(addr));
}

__device__ __forceinline__ void cp16(void* s, const void* g) {
    unsigned sa = (unsigned)__cvta_generic_to_shared(s);
    asm volatile("cp.async.cg.shared.global [%0], [%1], 16;" :: "r"(sa), "l"(g));
}
#define CP_COMMIT() asm volatile("cp.async.commit_group;")
#define CP_WAIT0()  asm volatile("cp.async.wait_group 0;")
#define CP_WAIT1()  asm volatile("cp.async.wait_group 1;")

__device__ __forceinline__ float ex2(float x) {
    float y;
    asm("ex2.approx.ftz.f32 %0, %1;" : "=f"(y) : "f"(x));
    return y;
}

__device__ __forceinline__ unsigned h2u(float a, float b) {
    __half2 h = __floats2half2_rn(a, b);
    return *(unsigned*)&h;
}

// ---------------------------------------------------------------------------
// fp32 -> fp16 bulk convert
// ---------------------------------------------------------------------------
__global__ __launch_bounds__(256)
void f2h_kernel(const float4* __restrict__ in, uint2* __restrict__ out, int n4)
{
    int i = blockIdx.x * blockDim.x + threadIdx.x;
    if (i < n4) {
        float4 a = in[i];
        out[i] = make_uint2(h2u(a.x, a.y), h2u(a.z, a.w));
    }
}

// ---------------------------------------------------------------------------
// RoPE cos/sin table
// ---------------------------------------------------------------------------
__global__ void rope_table_kernel()
{
    int i = blockIdx.x * blockDim.x + threadIdx.x;
    if (i < Tseq*32) {
        int tt = i >> 5, d = i & 31;
        float inv = 1.0f / powf(10000.0f, (float)d * (1.0f/32.0f));
        float ang = (float)tt * inv;
        g_cos[i] = cosf(ang);
        g_sin[i] = sinf(ang);
    }
}

// ---------------------------------------------------------------------------
// fp16 GEMM: C[M,N] = A[M,K]*B[N,K]^T, 128x128x32 tiles, 8 warps.
// cp.async 3-stage ring, ONE __syncthreads per k-chunk.
// ROPE=true: fused RoPE + head-scatter epilogue -> g_qh/kh/vh.
// ---------------------------------------------------------------------------
#define GSTR 40   // halves per smem row
#define GEMM_SMEM (3 * 2 * 128 * GSTR * 2)   // 3 stages * (A+B) * 128 rows * 80B

template<bool ROPE>
__global__ __launch_bounds__(256)
void gemm_h(const __half* __restrict__ A, const __half* __restrict__ Bw,
            float* __restrict__ C, int M, int N, int K)
{
    extern __shared__ __half smem[];
    __half* As = smem;                    // 3 stages of 128*GSTR
    __half* Bs = smem + 3*128*GSTR;

    const int tid = threadIdx.x;
    const int lane = tid & 31;
    const int wid = tid >> 5;
    const int g = lane >> 2;
    const int t = lane & 3;
    const int wm = wid & 3;
    const int wn = wid >> 2;
    const int bm = blockIdx.y * 128;
    const int bn = blockIdx.x * 128;

    const int lr = tid >> 1;          // 0..127
    const int lc = (tid & 1) * 16;    // 0 or 16 halves
    const __half* Ap = A + (size_t)(bm + lr) * K + lc;
    const __half* Bp = Bw + (size_t)(bn + lr) * K + lc;

    const int a_row = (lane & 7) + ((lane & 8) ? 8 : 0);
    const int a_col = (lane & 16) ? 8 : 0;
    const int b_row = (lane & 7) + ((lane & 16) ? 8 : 0);
    const int b_col = (lane & 8) ? 8 : 0;

    float c[2][8][4] = {};

    // prologue: stages 0 and 1
    #pragma unroll
    for (int p = 0; p < 2; p++) {
        cp16(&As[p*128*GSTR + lr*GSTR + lc],     Ap + p*32);
        cp16(&As[p*128*GSTR + lr*GSTR + lc + 8], Ap + p*32 + 8);
        cp16(&Bs[p*128*GSTR + lr*GSTR + lc],     Bp + p*32);
        cp16(&Bs[p*128*GSTR + lr*GSTR + lc + 8], Bp + p*32 + 8);
        CP_COMMIT();
    }

    const int NK = K / 32;   // 32
    for (int ks = 0; ks < NK; ks++) {
        if (ks < NK - 1) { CP_WAIT1(); } else { CP_WAIT0(); }
        __syncthreads();
        // prefetch ks+2 (safe: its buffer was read at iter ks-1, all warps past)
        if (ks + 2 < NK) {
            int sb = (ks + 2) % 3;
            int k0 = (ks + 2) * 32;
            cp16(&As[sb*128*GSTR + lr*GSTR + lc],     Ap + k0);
            cp16(&As[sb*128*GSTR + lr*GSTR + lc + 8], Ap + k0 + 8);
            cp16(&Bs[sb*128*GSTR + lr*GSTR + lc],     Bp + k0);
            cp16(&Bs[sb*128*GSTR + lr*GSTR + lc + 8], Bp + k0 + 8);
            CP_COMMIT();
        }
        const __half* as = &As[(ks % 3)*128*GSTR];
        const __half* bs = &Bs[(ks % 3)*128*GSTR];
        #pragma unroll
        for (int kc = 0; kc < 2; kc++) {
            unsigned aF[2][4];
            #pragma unroll
            for (int m = 0; m < 2; m++)
                ldsm_x4(aF[m], &as[(wm*32 + m*16 + a_row)*GSTR + kc*16 + a_col]);
            #pragma unroll
            for (int jp = 0; jp < 4; jp++) {
                unsigned bF[4];
                ldsm_x4(bF, &bs[(wn*64 + jp*16 + b_row)*GSTR + kc*16 + b_col]);
                mma_f16(c[0][2*jp],   aF[0], bF[0], bF[1]);
                mma_f16(c[0][2*jp+1], aF[0], bF[2], bF[3]);
                mma_f16(c[1][2*jp],   aF[1], bF[0], bF[1]);
                mma_f16(c[1][2*jp+1], aF[1], bF[2], bF[3]);
            }
        }
    }

    if (!ROPE) {
        #pragma unroll
        for (int m = 0; m < 2; m++) {
            size_t r0 = (size_t)(bm + wm*32 + m*16 + g);
            #pragma unroll
            for (int j = 0; j < 8; j++) {
                int cc = bn + wn*64 + j*8 + t*2;
                *(float2*)&C[r0*N + cc]     = make_float2(c[m][j][0], c[m][j][1]);
                *(float2*)&C[(r0+8)*N + cc] = make_float2(c[m][j][2], c[m][j][3]);
            }
        }
    } else {
        // fused RoPE + scatter. Thread's cols j and j+4 are the (d, d+32) pair.
        const int colb = bn + wn*64;   // 64-aligned -> one head
        #pragma unroll
        for (int m = 0; m < 2; m++) {
            #pragma unroll
            for (int rr = 0; rr < 2; rr++) {
                int row = bm + wm*32 + m*16 + g + rr*8;
                int e0 = rr*2;
                int tpos = row & (Tseq-1);
                int bi = row >> 11;
                if (colb < TOTQ) {
                    int h = colb >> 6;
                    __half* q = g_qh + ((size_t)(bi*HQ + h)*Tseq + tpos)*HD;
                    #pragma unroll
                    for (int j = 0; j < 4; j++) {
                        int d = j*8 + t*2;
                        float2 cs = *(const float2*)&g_cos[tpos*32 + d];
                        float2 sn = *(const float2*)&g_sin[tpos*32 + d];
                        float v1x = c[m][j][e0],   v1y = c[m][j][e0+1];
                        float v2x = c[m][j+4][e0], v2y = c[m][j+4][e0+1];
                        *(unsigned*)&q[d] = h2u((v1x*cs.x - v2x*sn.x)*QSCALE,
                                                (v1y*cs.y - v2y*sn.y)*QSCALE);
                        *(unsigned*)&q[d+32] = h2u((v2x*cs.x + v1x*sn.x)*QSCALE,
                                                   (v2y*cs.y + v1y*sn.y)*QSCALE);
                    }
                } else if (colb < TOTQ + TOTKV) {
                    int h = (colb - TOTQ) >> 6;
                    __half* k = g_kh + ((size_t)(bi*HKV + h)*Tseq + tpos)*HD;
                    #pragma unroll
                    for (int j = 0; j < 4; j++) {
                        int d = j*8 + t*2;
                        float2 cs = *(const float2*)&g_cos[tpos*32 + d];
                        float2 sn = *(const float2*)&g_sin[tpos*32 + d];
                        float v1x = c[m][j][e0],   v1y = c[m][j][e0+1];
                        float v2x = c[m][j+4][e0], v2y = c[m][j+4][e0+1];
                        *(unsigned*)&k[d] = h2u(v1x*cs.x - v2x*sn.x,
                                                v1y*cs.y - v2y*sn.y);
                        *(unsigned*)&k[d+32] = h2u(v2x*cs.x + v1x*sn.x,
                                                   v2y*cs.y + v1y*sn.y);
                    }
                } else {
                    int h = (colb - TOTQ - TOTKV) >> 6;
                    __half* v = g_vh + ((size_t)(bi*HKV + h)*Tseq + tpos)*HD;
                    #pragma unroll
                    for (int j = 0; j < 8; j++) {
                        int d = j*8 + t*2;
                        *(unsigned*)&v[d] = h2u(c[m][j][e0], c[m][j][e0+1]);
                    }
                }
            }
        }
    }
}

// ---------------------------------------------------------------------------
// fp16 causal flash attention, KV shared across GQA group.
// 1D grid, qt strictly descending globally: bid -> qt = 31 - bid/16,
// (b,hkv) = bid%16  => every wave holds near-equal-length CTAs.
// 512 threads / 16 warps: warp = (head, 16-row tile).
// cp.async 3-stage K/V ring, ONE __syncthreads per KV tile.
// Softmax in log2 domain (Q pre-scaled by 0.125*log2e).
// ---------------------------------------------------------------------------
#define KSTR 72     // halves per smem row
#define ATT_SMEM (3 * 2 * 64 * KSTR * 2)   // 3 stages * (K+V) * 64 rows * 144B

__global__ __launch_bounds__(512, 1)
void attn_tc()
{
    extern __shared__ __half smem[];
    __half* Ks = smem;                  // 3 stages of 64*KSTR
    __half* Vs = smem + 3*64*KSTR;

    const int bid = blockIdx.x;
    const int qt  = (Tseq/64 - 1) - (bid >> 4);   // 31..0, descending
    const int hb  = bid & 15;
    const int hkv = hb & 3;
    const int b   = hb >> 2;
    const int tid = threadIdx.x;
    const int lane = tid & 31;
    const int warp = tid >> 5;       // 0..15
    const int g = lane >> 2;
    const int t = lane & 3;
    const int h  = hkv*4 + (warp & 3);
    const int mt = warp >> 2;        // 0..3 -> 16-row tile within 64

    const int kb_row = (lane & 7) + ((lane & 16) ? 8 : 0);
    const int kb_col = (lane & 8) ? 8 : 0;
    const int vb_row = (lane & 7) + ((lane & 8) ? 8 : 0);
    const int vb_col = (lane & 16) ? 8 : 0;

    // Q fragments (half, pre-scaled by 0.125*log2e)
    const __half* Qg = g_qh + ((size_t)((b*HQ + h)*Tseq + qt*64 + mt*16))*HD;
    unsigned qa[4][4];
    #pragma unroll
    for (int kc = 0; kc < 4; kc++) {
        const __half* base = Qg + kc*16;
        qa[kc][0] = *(const unsigned*)&base[(g  )*HD + 2*t];
        qa[kc][1] = *(const unsigned*)&base[(g+8)*HD + 2*t];
        qa[kc][2] = *(const unsigned*)&base[(g  )*HD + 2*t + 8];
        qa[kc][3] = *(const unsigned*)&base[(g+8)*HD + 2*t + 8];
    }

    float o[8][4] = {};
    float mxA = -INFINITY, mxB = -INFINITY;
    float lsA = 0.f, lsB = 0.f;

    const __half* Kg0 = g_kh + ((size_t)(b*HKV + hkv)*Tseq)*HD;
    const __half* Vg0 = g_vh + ((size_t)(b*HKV + hkv)*Tseq)*HD;

    const int r  = tid >> 3;        // 0..63
    const int c0 = (tid & 7) * 8;   // halves (16B per thread)

    // prologue: stages 0 and (if present) 1
    cp16(&Ks[0*64*KSTR + r*KSTR + c0], Kg0 + (size_t)r*HD + c0);
    cp16(&Vs[0*64*KSTR + r*KSTR + c0], Vg0 + (size_t)r*HD + c0);
    CP_COMMIT();
    if (qt >= 1) {
        cp16(&Ks[1*64*KSTR + r*KSTR + c0], Kg0 + (size_t)(64 + r)*HD + c0);
        cp16(&Vs[1*64*KSTR + r*KSTR + c0], Vg0 + (size_t)(64 + r)*HD + c0);
        CP_COMMIT();
    }

    for (int j = 0; j <= qt; j++) {
        if (j < qt) { CP_WAIT1(); } else { CP_WAIT0(); }
        __syncthreads();
        // prefetch j+2 (its buffer was read at iter j-1; all warps past barrier)
        if (j + 2 <= qt) {
            int sb = (j + 2) % 3;
            cp16(&Ks[sb*64*KSTR + r*KSTR + c0], Kg0 + (size_t)((j+2)*64 + r)*HD + c0);
            cp16(&Vs[sb*64*KSTR + r*KSTR + c0], Vg0 + (size_t)((j+2)*64 + r)*HD + c0);
            CP_COMMIT();
        }
        const __half* ks = &Ks[(j % 3)*64*KSTR];
        const __half* vs = &Vs[(j % 3)*64*KSTR];

        // ---- S = Q*K^T (log2 domain) ----
        float s[8][4] = {};
        #pragma unroll
        for (int kc = 0; kc < 4; kc++) {
            #pragma unroll
            for (int jp = 0; jp < 4; jp++) {
                unsigned bF[4];
                ldsm_x4(bF, &ks[(jp*16 + kb_row)*KSTR + kc*16 + kb_col]);
                mma_f16(s[2*jp],   qa[kc], bF[0], bF[1]);
                mma_f16(s[2*jp+1], qa[kc], bF[2], bF[3]);
            }
        }

        if (j == qt) {   // causal mask within diagonal tile
            int rowA = mt*16 + g;   // local row within 64
            #pragma unroll
            for (int jn = 0; jn < 8; jn++) {
                #pragma unroll
                for (int e = 0; e < 2; e++) {
                    int col = jn*8 + t*2 + e;
                    if (col > rowA)     s[jn][e]   = -INFINITY;
                    if (col > rowA + 8) s[jn][2+e] = -INFINITY;
                }
            }
        }

        // ---- online softmax (base-2), rows g / g+8 ----
        float ma = -INFINITY, mb = -INFINITY;
        #pragma unroll
        for (int jn = 0; jn < 8; jn++) {
            ma = fmaxf(ma, fmaxf(s[jn][0], s[jn][1]));
            mb = fmaxf(mb, fmaxf(s[jn][2], s[jn][3]));
        }
        ma = fmaxf(ma, __shfl_xor_sync(0xffffffffu, ma, 1));
        ma = fmaxf(ma, __shfl_xor_sync(0xffffffffu, ma, 2));
        mb = fmaxf(mb, __shfl_xor_sync(0xffffffffu, mb, 1));
        mb = fmaxf(mb, __shfl_xor_sync(0xffffffffu, mb, 2));

        float mnA = fmaxf(mxA, ma), mnB = fmaxf(mxB, mb);
        float cA = ex2(mxA - mnA), cB = ex2(mxB - mnB);

        float la = 0.f, lb = 0.f;
        #pragma unroll
        for (int jn = 0; jn < 8; jn++) {
            s[jn][0] = ex2(s[jn][0] - mnA);
            s[jn][1] = ex2(s[jn][1] - mnA);
            s[jn][2] = ex2(s[jn][2] - mnB);
            s[jn][3] = ex2(s[jn][3] - mnB);
            la += s[jn][0] + s[jn][1];
            lb += s[jn][2] + s[jn][3];
        }
        la += __shfl_xor_sync(0xffffffffu, la, 1);
        la += __shfl_xor_sync(0xffffffffu, la, 2);
        lb += __shfl_xor_sync(0xffffffffu, lb, 1);
        lb += __shfl_xor_sync(0xffffffffu, lb, 2);
        lsA = lsA*cA + la;  mxA = mnA;
        lsB = lsB*cB + lb;  mxB = mnB;

        #pragma unroll
        for (int jd = 0; jd < 8; jd++) {
            o[jd][0] *= cA; o[jd][1] *= cA;
            o[jd][2] *= cB; o[jd][3] *= cB;
        }

        // pack P as fp16 A-fragments
        unsigned pa[4][4];
        #pragma unroll
        for (int kc = 0; kc < 4; kc++) {
            pa[kc][0] = h2u(s[2*kc][0],   s[2*kc][1]);
            pa[kc][1] = h2u(s[2*kc][2],   s[2*kc][3]);
            pa[kc][2] = h2u(s[2*kc+1][0], s[2*kc+1][1]);
            pa[kc][3] = h2u(s[2*kc+1][2], s[2*kc+1][3]);
        }

        // ---- O += P*V (V B-frags via ldmatrix.trans) ----
        #pragma unroll
        for (int kc = 0; kc < 4; kc++) {
            #pragma unroll
            for (int jp = 0; jp < 4; jp++) {
                unsigned bF[4];
                ldsm_x4_t(bF, &vs[(kc*16 + vb_row)*KSTR + jp*16 + vb_col]);
                mma_f16(o[2*jp],   pa[kc], bF[0], bF[1]);
                mma_f16(o[2*jp+1], pa[kc], bF[2], bF[3]);
            }
        }
    }

    // epilogue: normalize + store half
    const float invA = 1.f / lsA, invB = 1.f / lsB;
    size_t row0 = (size_t)(b*Tseq + qt*64 + mt*16 + g);
    __half* op = g_attnh + row0*TOTQ + h*HD;
    #pragma unroll
    for (int jd = 0; jd < 8; jd++) {
        int col = jd*8 + t*2;
        *(unsigned*)&op[col] = h2u(o[jd][0]*invA, o[jd][1]*invA);
        *(unsigned*)&op[(size_t)8*TOTQ + col] = h2u(o[jd][2]*invB, o[jd][3]*invB);
    }
}

// ---------------------------------------------------------------------------
extern "C" void kernel_launch(void* const* d_in, const int* in_sizes, int n_in,
                              void* d_out, int out_size)
{
    const float* x     = (const float*)d_in[0];
    const float* w_qkv = (const float*)d_in[1];
    const float* w_out = (const float*)d_in[2];
    float* out = (float*)d_out;

    __half *xh, *wqkvh, *wouth, *attnh;
    cudaGetSymbolAddress((void**)&xh, g_xh);
    cudaGetSymbolAddress((void**)&wqkvh, g_wqkvh);
    cudaGetSymbolAddress((void**)&wouth, g_wouth);
    cudaGetSymbolAddress((void**)&attnh, g_attnh);

    // idempotent host-side attribute sets (cheap; no static guards allowed)
    cudaFuncSetAttribute(gemm_h<true>,
        cudaFuncAttributeMaxDynamicSharedMemorySize, GEMM_SMEM);
    cudaFuncSetAttribute(gemm_h<false>,
        cudaFuncAttributeMaxDynamicSharedMemorySize, GEMM_SMEM);
    cudaFuncSetAttribute(attn_tc,
        cudaFuncAttributeMaxDynamicSharedMemorySize, ATT_SMEM);

    // 0) rope table + fp16 conversions
    rope_table_kernel<<<64, 1024>>>();
    f2h_kernel<<<(Mrows*Emb/4 + 255)/256, 256>>>((const float4*)x, (uint2*)xh, Mrows*Emb/4);
    f2h_kernel<<<(Fqkv*Emb/4 + 255)/256, 256>>>((const float4*)w_qkv, (uint2*)wqkvh, Fqkv*Emb/4);
    f2h_kernel<<<(TOTQ*Emb/4 + 255)/256, 256>>>((const float4*)w_out, (uint2*)wouth, TOTQ*Emb/4);

    // 1) QKV projection with fused RoPE + head scatter
    gemm_h<true><<<dim3(Fqkv/128, Mrows/128), 256, GEMM_SMEM>>>(xh, wqkvh, nullptr,
                                                                Mrows, Fqkv, Emb);
    // 2) causal GQA flash attention (1D grid, qt descending globally)
    attn_tc<<<(Tseq/64) * HKV * Bsz, 512, ATT_SMEM>>>();

    // 3) output projection
    gemm_h<false><<<dim3(TOTQ/128, Mrows/128), 256, GEMM_SMEM>>>(attnh, wouth, out,
                                                                 Mrows, TOTQ, Emb);
}